// round 12
// baseline (speedup 1.0000x reference)
#include <cuda_runtime.h>
#include <cuda_fp16.h>
#include <cstdint>
#include <math.h>

#define BB   4
#define SEQ  2048
#define CDIM 1024
#define NH   16
#define HD   64
#define MROWS (BB*SEQ)
#define KDIM 1024
#define NQKV 3072
#define BK   64
#define PADK 72
#define NCHUNK_QKV 16          // K' = 1024/64
#define NCHUNK_PROJ 16

#define GEMM_STAGE (128*PADK*2)            // 18432 B per tile per stage
#define GEMM_SMEM  (4*GEMM_STAGE)          // 73728 B (A0,A1,B0,B1)

// attention smem geometry
#define QROWB 144
#define QSMEM_BYTES (128*QROWB)            // 18432
#define KROWB 144
#define KTILE (64*KROWB)                   // 9216
#define VROWB 144
#define VTILE (64*VROWB)                   // 9216
#define KVBUF (KTILE+VTILE)                // 18432
#define ATTN_SMEM (QSMEM_BYTES + 2*KVBUF)  // 55296

#define QSCALE 0.1803368801111179f         // 0.125 * log2(e)

// ---------------- scratch ----------------
__device__ __half g_Qh[BB*NH*SEQ*HD];      // [B,H,N,D] fp16, pre-scaled
__device__ __half g_Kh[BB*NH*SEQ*HD];
__device__ __half g_Vh[BB*NH*SEQ*HD];
__device__ __half g_Ah[MROWS*KDIM];        // x single fp16
__device__ __half g_Wq[NQKV*KDIM];         // W_qkv^T single fp16 [N,K]
__device__ __half g_Oh[MROWS*CDIM];        // attention out single fp16 [B,N,H*D]
__device__ __half g_Wp[CDIM*KDIM];         // W_proj^T single fp16 [N,K]

// ---------------- helpers ----------------
typedef unsigned long long ull;

__device__ __forceinline__ uint32_t smem_u32(const void* p) {
    return (uint32_t)__cvta_generic_to_shared(p);
}
__device__ __forceinline__ ull ffma2(ull a, ull b, ull c) {
    ull d; asm("fma.rn.f32x2 %0, %1, %2, %3;" : "=l"(d) : "l"(a), "l"(b), "l"(c)); return d;
}
__device__ __forceinline__ ull add2(ull a, ull b) {
    ull d; asm("add.rn.f32x2 %0, %1, %2;" : "=l"(d) : "l"(a), "l"(b)); return d;
}
__device__ __forceinline__ ull pack2(float lo, float hi) {
    ull r; asm("mov.b64 %0, {%1, %2};" : "=l"(r) : "f"(lo), "f"(hi)); return r;
}
__device__ __forceinline__ float2 unpack2(ull v) {
    float lo, hi; asm("mov.b64 {%0, %1}, %2;" : "=f"(lo), "=f"(hi) : "l"(v));
    return make_float2(lo, hi);
}
__device__ __forceinline__ void cp16(uint32_t dst, const void* src) {
    asm volatile("cp.async.cg.shared.global [%0], [%1], 16;" :: "r"(dst), "l"(src));
}
__device__ __forceinline__ void cp_commit() { asm volatile("cp.async.commit_group;"); }
__device__ __forceinline__ void ldm_x4(uint32_t* r, uint32_t addr) {
    asm volatile("ldmatrix.sync.aligned.m8n8.x4.shared.b16 {%0,%1,%2,%3}, [%4];"
                 : "=r"(r[0]), "=r"(r[1]), "=r"(r[2]), "=r"(r[3]) : "r"(addr));
}
__device__ __forceinline__ void ldm_x4_t(uint32_t* r, uint32_t addr) {
    asm volatile("ldmatrix.sync.aligned.m8n8.x4.trans.shared.b16 {%0,%1,%2,%3}, [%4];"
                 : "=r"(r[0]), "=r"(r[1]), "=r"(r[2]), "=r"(r[3]) : "r"(addr));
}
__device__ __forceinline__ void mma_fp(float* c, const uint32_t* a, const uint32_t* b) {
    asm volatile(
        "mma.sync.aligned.m16n8k16.row.col.f32.f16.f16.f32 "
        "{%0,%1,%2,%3}, {%4,%5,%6,%7}, {%8,%9}, {%0,%1,%2,%3};"
        : "+f"(c[0]), "+f"(c[1]), "+f"(c[2]), "+f"(c[3])
        : "r"(a[0]), "r"(a[1]), "r"(a[2]), "r"(a[3]), "r"(b[0]), "r"(b[1]));
}
__device__ __forceinline__ void store_h2(__half* A, size_t idx, float v0, float v1) {
    uint32_t r; asm("cvt.rn.f16x2.f32 %0, %1, %2;" : "=r"(r) : "f"(v1), "f"(v0));
    *(uint32_t*)&A[idx] = r;
}
__device__ __forceinline__ uint32_t h2pack(float2 v) {
    uint32_t r; asm("cvt.rn.f16x2.f32 %0, %1, %2;" : "=r"(r) : "f"(v.y), "f"(v.x));
    return r;
}

#define MAGICF 12582912.0f
__device__ __forceinline__ ull exp2pair(ull t) {
    const ull MAGIC2  = pack2(MAGICF, MAGICF);
    const ull NMAGIC2 = pack2(-MAGICF, -MAGICF);
    const ull NONE2   = pack2(-1.0f, -1.0f);
    const ull ONE2    = pack2(1.0f, 1.0f);
    const ull C1 = pack2(0.6931471805599453f, 0.6931471805599453f);
    const ull C2 = pack2(0.2402265069591007f, 0.2402265069591007f);
    const ull C3 = pack2(0.05550410866482158f, 0.05550410866482158f);
    const ull C4 = pack2(0.009618129107628477f, 0.009618129107628477f);
    const ull C5 = pack2(0.0013333558146428443f, 0.0013333558146428443f);
    ull m = add2(t, MAGIC2);
    ull kf = add2(m, NMAGIC2);
    ull f = ffma2(kf, NONE2, t);
    ull p = ffma2(C5, f, C4);
    p = ffma2(p, f, C3); p = ffma2(p, f, C2); p = ffma2(p, f, C1); p = ffma2(p, f, ONE2);
    float2 mf = unpack2(m); float2 pf = unpack2(p);
    uint32_t r0 = __float_as_uint(pf.x) + (__float_as_uint(mf.x) << 23);
    uint32_t r1 = __float_as_uint(pf.y) + (__float_as_uint(mf.y) << 23);
    return pack2(__uint_as_float(r0), __uint_as_float(r1));
}

// ---------------- conversion kernels ----------------
__global__ void conv_x(const float* __restrict__ src, int n4)
{
    int i = blockIdx.x * blockDim.x + threadIdx.x;
    if (i >= n4) return;
    float4 v = ((const float4*)src)[i];
    union { uint2 u; __half h[4]; } ph;
    ph.h[0] = __float2half_rn(v.x);
    ph.h[1] = __float2half_rn(v.y);
    ph.h[2] = __float2half_rn(v.z);
    ph.h[3] = __float2half_rn(v.w);
    ((uint2*)g_Ah)[i] = ph.u;
}

// transpose W -> single fp16 plane [N,K]; SEL 0 -> Wq, 1 -> Wp
template <int SEL>
__global__ void conv_w(const float* __restrict__ W, int Nd)
{
    __shared__ float t[32][33];
    __half* dst = SEL ? g_Wp : g_Wq;
    int n0 = blockIdx.x * 32, k0 = blockIdx.y * 32;
    #pragma unroll
    for (int i = 0; i < 4; i++) {
        int k = k0 + threadIdx.y + i * 8;
        t[threadIdx.y + i * 8][threadIdx.x] = W[(size_t)k * Nd + n0 + threadIdx.x];
    }
    __syncthreads();
    #pragma unroll
    for (int i = 0; i < 4; i++) {
        int n = n0 + threadIdx.y + i * 8;
        int k = k0 + threadIdx.x;
        dst[(size_t)n * KDIM + k] = __float2half_rn(t[threadIdx.x][threadIdx.y + i * 8]);
    }
}

// ---------------- fp16 GEMM on mma.sync: 128x128 tile, BK=64, warp 64x32 -------
// MODE 0: QKV — A = g_Ah, B = g_Wq, epilogue scatter to Q/K/V.
// MODE 1: proj — A = g_Oh, B = g_Wp, out fp32 + bias.
template <int MODE>
__global__ __launch_bounds__(256, 2)
void gemm_fp16(const float* __restrict__ bias, float* __restrict__ out)
{
    constexpr int NCH = (MODE == 0) ? NCHUNK_QKV : NCHUNK_PROJ;
    extern __shared__ char gsm[];

    const int tid = threadIdx.x;
    const int lane = tid & 31, wid = tid >> 5;
    const int warp_m = wid >> 2, warp_n = wid & 3;
    const int mTile = blockIdx.y, nTile = blockIdx.x;
    const int aRow0 = mTile * 128, bRow0 = nTile * 128;
    const int lrow = tid >> 1, lhalf = tid & 1;

    const uint32_t asBase = smem_u32(gsm);
    const uint32_t bsBase = asBase + 2 * GEMM_STAGE;

    auto load_chunk = [&](int kc) {
        int k0 = kc * BK;
        const __half* Ap = (MODE == 0) ? g_Ah : g_Oh;
        const __half* Bp = (MODE == 0) ? g_Wq : g_Wp;
        uint32_t so = (uint32_t)(kc & 1) * GEMM_STAGE;
        uint32_t doff = so + (uint32_t)lrow * (PADK * 2) + (uint32_t)lhalf * 64;
        const __half* asrc = Ap + (size_t)(aRow0 + lrow) * KDIM + k0 + lhalf * 32;
        const __half* bsrc = Bp + (size_t)(bRow0 + lrow) * KDIM + k0 + lhalf * 32;
        #pragma unroll
        for (int i = 0; i < 4; i++) {
            cp16(asBase + doff + i * 16, asrc + i * 8);
            cp16(bsBase + doff + i * 16, bsrc + i * 8);
        }
        cp_commit();
    };

    float acc[4][4][4];
    #pragma unroll
    for (int mi = 0; mi < 4; mi++)
        #pragma unroll
        for (int ni = 0; ni < 4; ni++)
            #pragma unroll
            for (int q = 0; q < 4; q++) acc[mi][ni][q] = 0.0f;

    load_chunk(0);
    load_chunk(1);

    const int aRowL = warp_m * 64 + (lane & 15);
    const int aKoff = (lane >> 4) << 3;
    const int bRowL = warp_n * 32 + ((lane >> 4) << 3) + (lane & 7);
    const int bKoff = ((lane >> 3) & 1) << 3;

    #pragma unroll 1
    for (int kc = 0; kc < NCH; ++kc) {
        if (kc == NCH - 1) asm volatile("cp.async.wait_group 0;" ::: "memory");
        else               asm volatile("cp.async.wait_group 1;" ::: "memory");
        __syncthreads();

        uint32_t ab = asBase + (uint32_t)(kc & 1) * GEMM_STAGE;
        uint32_t bb = bsBase + (uint32_t)(kc & 1) * GEMM_STAGE;

        #pragma unroll
        for (int ksh = 0; ksh < 2; ksh++) {
            // phase 1: all fragment loads for 2 k-steps
            uint32_t a_r[2][4][4];
            uint32_t b_r[2][4][2];
            #pragma unroll
            for (int k2 = 0; k2 < 2; k2++) {
                int ks = ksh * 2 + k2;
                #pragma unroll
                for (int mi = 0; mi < 4; mi++)
                    ldm_x4(a_r[k2][mi], ab + (uint32_t)(aRowL + mi * 16) * (PADK * 2)
                                          + (uint32_t)(ks * 16 + aKoff) * 2);
                #pragma unroll
                for (int np = 0; np < 2; np++) {
                    uint32_t r[4];
                    ldm_x4(r, bb + (uint32_t)(bRowL + np * 16) * (PADK * 2)
                                + (uint32_t)(ks * 16 + bKoff) * 2);
                    b_r[k2][np*2][0] = r[0]; b_r[k2][np*2][1] = r[1];
                    b_r[k2][np*2+1][0] = r[2]; b_r[k2][np*2+1][1] = r[3];
                }
            }
            // phase 2: all mma
            #pragma unroll
            for (int k2 = 0; k2 < 2; k2++)
                #pragma unroll
                for (int mi = 0; mi < 4; mi++)
                    #pragma unroll
                    for (int ni = 0; ni < 4; ni++)
                        mma_fp(acc[mi][ni], a_r[k2][mi], b_r[k2][ni]);
        }

        __syncthreads();
        if (kc + 2 < NCH) load_chunk(kc + 2);
    }

    const int mBase = mTile * 128 + warp_m * 64;
    const int nBase = nTile * 128 + warp_n * 32;
    const int rq = lane >> 2, cq = (lane & 3) * 2;

    if (MODE == 0) {
        const int part = (nTile * 128) >> 10;   // 0=Q, 1=K, 2=V
        #pragma unroll
        for (int mi = 0; mi < 4; mi++)
            #pragma unroll
            for (int ni = 0; ni < 4; ni++) {
                int col = nBase + ni * 8 + cq;
                float2 bv = *(const float2*)&bias[col];
                int h = (col & 1023) >> 6, d = col & 63;
                #pragma unroll
                for (int h2 = 0; h2 < 2; h2++) {
                    int row = mBase + mi * 16 + rq + h2 * 8;
                    int b = row >> 11, n = row & 2047;
                    size_t idx = (((size_t)(b * NH + h)) * SEQ + n) * HD + d;
                    float v0 = acc[mi][ni][h2*2]   + bv.x;
                    float v1 = acc[mi][ni][h2*2+1] + bv.y;
                    if (part == 0)      store_h2(g_Qh, idx, v0 * QSCALE, v1 * QSCALE);
                    else if (part == 1) store_h2(g_Kh, idx, v0, v1);
                    else                store_h2(g_Vh, idx, v0, v1);
                }
            }
    } else {
        #pragma unroll
        for (int mi = 0; mi < 4; mi++)
            #pragma unroll
            for (int ni = 0; ni < 4; ni++) {
                int col = nBase + ni * 8 + cq;
                float2 bv = *(const float2*)&bias[col];
                #pragma unroll
                for (int h2 = 0; h2 < 2; h2++) {
                    int row = mBase + mi * 16 + rq + h2 * 8;
                    float2 v = make_float2(acc[mi][ni][h2*2] + bv.x,
                                           acc[mi][ni][h2*2+1] + bv.y);
                    *(float2*)&out[(size_t)row * CDIM + col] = v;
                }
            }
    }
}

// ---------------- tensor-core flash attention: fp16 QK, fp16 single-term PV ------
__global__ __launch_bounds__(128)
void attn_mma()
{
    extern __shared__ char sm_[];
    const int tid  = threadIdx.x;
    const int lane = tid & 31, wid = tid >> 5;
    const int bh = blockIdx.y, qt = blockIdx.x;
    const int b = bh >> 4, h = bh & 15;

    const uint32_t QS  = smem_u32(sm_);
    const uint32_t KV0 = QS + QSMEM_BYTES;
    const size_t ghead = (size_t)bh * SEQ * HD;

    {   // Q tile: 128 rows x 64 fp16
        const __half* qs = g_Qh + ghead + ((size_t)qt * 128 + tid) * HD;
        uint32_t dst = QS + (uint32_t)tid * QROWB;
        #pragma unroll
        for (int s = 0; s < 8; s++) cp16(dst + s*16, qs + s*8);
        cp_commit();
    }

    auto load_kv = [&](int kt) {
        int r = tid >> 1, half = tid & 1;
        const size_t grow = ghead + ((size_t)kt * 64 + r) * HD + half * 32;
        const uint32_t base = KV0 + (uint32_t)(kt & 1) * KVBUF;
        uint32_t kdst = base + (uint32_t)r * KROWB + (uint32_t)half * 64;
        const __half* ks = g_Kh + grow;
        #pragma unroll
        for (int i = 0; i < 4; i++) cp16(kdst + i*16, ks + i*8);
        uint32_t vdst = base + KTILE + (uint32_t)r * VROWB + (uint32_t)half * 64;
        const __half* vs = g_Vh + grow;
        #pragma unroll
        for (int i = 0; i < 4; i++) cp16(vdst + i*16, vs + i*8);
        cp_commit();
    };
    load_kv(0);
    load_kv(1);

    asm volatile("cp.async.wait_group 2;" ::: "memory");
    __syncthreads();

    const int wrow = wid * 32;
    uint32_t qf[2][4][4];
    #pragma unroll
    for (int mi = 0; mi < 2; mi++) {
        uint32_t rowa = QS + (uint32_t)(wrow + mi*16 + (lane & 15)) * QROWB
                      + (uint32_t)((lane >> 4) << 4);
        #pragma unroll
        for (int k = 0; k < 4; k++) ldm_x4(qf[mi][k], rowa + k*32);
    }

    float oc[2][8][4];
    #pragma unroll
    for (int mi = 0; mi < 2; mi++)
        #pragma unroll
        for (int n = 0; n < 8; n++)
            #pragma unroll
            for (int q = 0; q < 4; q++) oc[mi][n][q] = 0.0f;
    ull lacc[2][2];
    lacc[0][0] = lacc[0][1] = lacc[1][0] = lacc[1][1] = pack2(0.0f, 0.0f);

    #pragma unroll 1
    for (int kt = 0; kt < SEQ/64; ++kt) {
        asm volatile("cp.async.wait_group 1;" ::: "memory");
        __syncthreads();

        const uint32_t Kb = KV0 + (uint32_t)(kt & 1) * KVBUF;
        const uint32_t Vb = Kb + KTILE;

        float sc[2][8][4];
        #pragma unroll
        for (int mi = 0; mi < 2; mi++)
            #pragma unroll
            for (int n = 0; n < 8; n++)
                #pragma unroll
                for (int q = 0; q < 4; q++) sc[mi][n][q] = 0.0f;

        #pragma unroll
        for (int kk = 0; kk < 4; kk++) {
            uint32_t br[4][4];
            #pragma unroll
            for (int np = 0; np < 4; np++)
                ldm_x4(br[np], Kb + (uint32_t)(np*16 + ((lane >> 4) << 3) + (lane & 7)) * KROWB
                                 + (uint32_t)(kk*16 + (((lane >> 3) & 1) << 3)) * 2);
            #pragma unroll
            for (int mi = 0; mi < 2; mi++) {
                #pragma unroll
                for (int np = 0; np < 4; np++) {
                    mma_fp(sc[mi][np*2],   qf[mi][kk], &br[np][0]);
                    mma_fp(sc[mi][np*2+1], qf[mi][kk], &br[np][2]);
                }
            }
        }

        // exp2 -> P (single fp16) -> PV (single term)
        #pragma unroll
        for (int kk = 0; kk < 4; kk++) {
            uint32_t aP[2][4];
            #pragma unroll
            for (int mi = 0; mi < 2; mi++) {
                #pragma unroll
                for (int half = 0; half < 2; half++) {
                    int n = 2*kk + half;
                    ull p01 = exp2pair(pack2(sc[mi][n][0], sc[mi][n][1]));
                    ull p23 = exp2pair(pack2(sc[mi][n][2], sc[mi][n][3]));
                    lacc[mi][0] = add2(lacc[mi][0], p01);
                    lacc[mi][1] = add2(lacc[mi][1], p23);
                    aP[mi][half*2]   = h2pack(unpack2(p01));
                    aP[mi][half*2+1] = h2pack(unpack2(p23));
                }
            }
            const uint32_t krow = (uint32_t)(kk*16 + ((lane >> 3) & 1) * 8 + (lane & 7));
            #pragma unroll
            for (int nb = 0; nb < 4; nb++) {
                uint32_t bv[4];
                ldm_x4_t(bv, Vb + krow * VROWB + (uint32_t)(nb*16 + ((lane >> 4) << 3)) * 2);
                #pragma unroll
                for (int mi = 0; mi < 2; mi++) {
                    mma_fp(oc[mi][nb*2],   aP[mi], &bv[0]);
                    mma_fp(oc[mi][nb*2+1], aP[mi], &bv[2]);
                }
            }
        }
        __syncthreads();
        if (kt + 2 < SEQ/64) load_kv(kt + 2);
    }

    // normalize + single-fp16 write to [B,N,H*D]
    #pragma unroll
    for (int mi = 0; mi < 2; mi++) {
        float2 L0 = unpack2(lacc[mi][0]);
        float l0 = L0.x + L0.y;
        l0 += __shfl_xor_sync(0xFFFFFFFFu, l0, 1);
        l0 += __shfl_xor_sync(0xFFFFFFFFu, l0, 2);
        float2 L1 = unpack2(lacc[mi][1]);
        float l1 = L1.x + L1.y;
        l1 += __shfl_xor_sync(0xFFFFFFFFu, l1, 1);
        l1 += __shfl_xor_sync(0xFFFFFFFFu, l1, 2);
        float inv0 = 1.0f / l0, inv1 = 1.0f / l1;
        int r0 = qt * 128 + wrow + mi*16 + (lane >> 2);
        #pragma unroll
        for (int ni = 0; ni < 8; ni++) {
            int d = ni*8 + (lane & 3)*2;
            size_t i0 = ((size_t)(b * SEQ + r0)) * CDIM + h * HD + d;
            size_t i1 = ((size_t)(b * SEQ + r0 + 8)) * CDIM + h * HD + d;
            store_h2(g_Oh, i0, oc[mi][ni][0]*inv0, oc[mi][ni][1]*inv0);
            store_h2(g_Oh, i1, oc[mi][ni][2]*inv1, oc[mi][ni][3]*inv1);
        }
    }
}

// ---------------- launch ----------------
extern "C" void kernel_launch(void* const* d_in, const int* in_sizes, int n_in,
                              void* d_out, int out_size)
{
    const float* x      = (const float*)d_in[0];
    const float* W_qkv  = (const float*)d_in[1];
    const float* b_qkv  = (const float*)d_in[2];
    const float* W_proj = (const float*)d_in[3];
    const float* b_proj = (const float*)d_in[4];
    float* out = (float*)d_out;

    cudaFuncSetAttribute(attn_mma, cudaFuncAttributeMaxDynamicSharedMemorySize, ATTN_SMEM);
    cudaFuncSetAttribute(gemm_fp16<0>, cudaFuncAttributeMaxDynamicSharedMemorySize, GEMM_SMEM);
    cudaFuncSetAttribute(gemm_fp16<1>, cudaFuncAttributeMaxDynamicSharedMemorySize, GEMM_SMEM);

    conv_x<<<(MROWS * KDIM / 4 + 255) / 256, 256>>>(x, MROWS * KDIM / 4);
    {
        dim3 bdim(32, 8);
        dim3 gq(NQKV / 32, KDIM / 32);
        conv_w<0><<<gq, bdim>>>(W_qkv, NQKV);
        dim3 gp(CDIM / 32, KDIM / 32);
        conv_w<1><<<gp, bdim>>>(W_proj, CDIM);
    }
    {
        dim3 g(NQKV / 128, MROWS / 128);
        gemm_fp16<0><<<g, 256, GEMM_SMEM>>>(b_qkv, nullptr);
    }
    {
        dim3 ga(SEQ / 128, BB * NH);
        attn_mma<<<ga, 128, ATTN_SMEM>>>();
    }
    {
        dim3 g(CDIM / 128, MROWS / 128);
        gemm_fp16<1><<<g, 256, GEMM_SMEM>>>(b_proj, out);
    }
}

// round 13
// speedup vs baseline: 1.1386x; 1.1386x over previous
#include <cuda_runtime.h>
#include <cuda_fp16.h>
#include <cstdint>
#include <math.h>

#define BB   4
#define SEQ  2048
#define CDIM 1024
#define NH   16
#define HD   64
#define MROWS (BB*SEQ)
#define KDIM 1024
#define NQKV 3072
#define BK   32
#define PADK 40
#define NCHUNK_QKV 32          // K' = 1024/32 (single fp16 term)
#define NCHUNK_PROJ 32         // K' = 1024/32 (single fp16 term)

// attention smem geometry
#define QROWB 144
#define QSMEM_BYTES (128*QROWB)            // 18432
#define KROWB 144
#define KTILE (64*KROWB)                   // 9216
#define VROWB 144
#define VTILE (64*VROWB)                   // 9216
#define KVBUF (KTILE+VTILE)                // 18432
#define ATTN_SMEM (QSMEM_BYTES + 2*KVBUF)  // 55296

#define QSCALE 0.1803368801111179f         // 0.125 * log2(e)

// ---------------- scratch ----------------
__device__ __half g_Qh[BB*NH*SEQ*HD];      // [B,H,N,D] fp16, pre-scaled
__device__ __half g_Kh[BB*NH*SEQ*HD];
__device__ __half g_Vh[BB*NH*SEQ*HD];
__device__ __half g_Ah[MROWS*KDIM];        // x single fp16
__device__ __half g_Wq[NQKV*KDIM];         // W_qkv^T single fp16 [N,K]
__device__ __half g_Oh[MROWS*CDIM];        // attention out single fp16 [B,N,H*D]
__device__ __half g_Wp[CDIM*KDIM];         // W_proj^T single fp16 [N,K]

// ---------------- helpers ----------------
typedef unsigned long long ull;

__device__ __forceinline__ uint32_t smem_u32(const void* p) {
    return (uint32_t)__cvta_generic_to_shared(p);
}
__device__ __forceinline__ ull ffma2(ull a, ull b, ull c) {
    ull d; asm("fma.rn.f32x2 %0, %1, %2, %3;" : "=l"(d) : "l"(a), "l"(b), "l"(c)); return d;
}
__device__ __forceinline__ ull add2(ull a, ull b) {
    ull d; asm("add.rn.f32x2 %0, %1, %2;" : "=l"(d) : "l"(a), "l"(b)); return d;
}
__device__ __forceinline__ ull pack2(float lo, float hi) {
    ull r; asm("mov.b64 %0, {%1, %2};" : "=l"(r) : "f"(lo), "f"(hi)); return r;
}
__device__ __forceinline__ float2 unpack2(ull v) {
    float lo, hi; asm("mov.b64 {%0, %1}, %2;" : "=f"(lo), "=f"(hi) : "l"(v));
    return make_float2(lo, hi);
}
__device__ __forceinline__ void cp16(uint32_t dst, const void* src) {
    asm volatile("cp.async.cg.shared.global [%0], [%1], 16;" :: "r"(dst), "l"(src));
}
__device__ __forceinline__ void cp_commit() { asm volatile("cp.async.commit_group;"); }
__device__ __forceinline__ void ldm_x4(uint32_t* r, uint32_t addr) {
    asm volatile("ldmatrix.sync.aligned.m8n8.x4.shared.b16 {%0,%1,%2,%3}, [%4];"
                 : "=r"(r[0]), "=r"(r[1]), "=r"(r[2]), "=r"(r[3]) : "r"(addr));
}
__device__ __forceinline__ void ldm_x4_t(uint32_t* r, uint32_t addr) {
    asm volatile("ldmatrix.sync.aligned.m8n8.x4.trans.shared.b16 {%0,%1,%2,%3}, [%4];"
                 : "=r"(r[0]), "=r"(r[1]), "=r"(r[2]), "=r"(r[3]) : "r"(addr));
}
__device__ __forceinline__ void mma_fp(float* c, const uint32_t* a, const uint32_t* b) {
    asm volatile(
        "mma.sync.aligned.m16n8k16.row.col.f32.f16.f16.f32 "
        "{%0,%1,%2,%3}, {%4,%5,%6,%7}, {%8,%9}, {%0,%1,%2,%3};"
        : "+f"(c[0]), "+f"(c[1]), "+f"(c[2]), "+f"(c[3])
        : "r"(a[0]), "r"(a[1]), "r"(a[2]), "r"(a[3]), "r"(b[0]), "r"(b[1]));
}
__device__ __forceinline__ void store_h2(__half* A, size_t idx, float v0, float v1) {
    uint32_t r; asm("cvt.rn.f16x2.f32 %0, %1, %2;" : "=r"(r) : "f"(v1), "f"(v0));
    *(uint32_t*)&A[idx] = r;
}
__device__ __forceinline__ uint32_t h2pack(float2 v) {
    uint32_t r; asm("cvt.rn.f16x2.f32 %0, %1, %2;" : "=r"(r) : "f"(v.y), "f"(v.x));
    return r;
}

#define MAGICF 12582912.0f
// degree-4 2^f poly on f in [-0.5, 0.5]; max rel err ~1e-6 (invisible under fp16 P)
__device__ __forceinline__ ull exp2pair(ull t) {
    const ull MAGIC2  = pack2(MAGICF, MAGICF);
    const ull NMAGIC2 = pack2(-MAGICF, -MAGICF);
    const ull NONE2   = pack2(-1.0f, -1.0f);
    const ull ONE2    = pack2(1.0f, 1.0f);
    const ull C1 = pack2(0.6931471971938464f, 0.6931471971938464f);
    const ull C2 = pack2(0.2402264689063408f, 0.2402264689063408f);
    const ull C3 = pack2(0.0555042108516768f, 0.0555042108516768f);
    const ull C4 = pack2(0.0096181289721693f, 0.0096181289721693f);
    ull m = add2(t, MAGIC2);
    ull kf = add2(m, NMAGIC2);
    ull f = ffma2(kf, NONE2, t);
    ull p = ffma2(C4, f, C3);
    p = ffma2(p, f, C2); p = ffma2(p, f, C1); p = ffma2(p, f, ONE2);
    float2 mf = unpack2(m); float2 pf = unpack2(p);
    uint32_t r0 = __float_as_uint(pf.x) + (__float_as_uint(mf.x) << 23);
    uint32_t r1 = __float_as_uint(pf.y) + (__float_as_uint(mf.y) << 23);
    return pack2(__uint_as_float(r0), __uint_as_float(r1));
}

// ---------------- conversion kernels ----------------
__global__ void conv_x(const float* __restrict__ src, int n4)
{
    int i = blockIdx.x * blockDim.x + threadIdx.x;
    if (i >= n4) return;
    float4 v = ((const float4*)src)[i];
    union { uint2 u; __half h[4]; } ph;
    ph.h[0] = __float2half_rn(v.x);
    ph.h[1] = __float2half_rn(v.y);
    ph.h[2] = __float2half_rn(v.z);
    ph.h[3] = __float2half_rn(v.w);
    ((uint2*)g_Ah)[i] = ph.u;
}

// transpose W -> single fp16 plane [N,K]; SEL 0 -> Wq, 1 -> Wp
template <int SEL>
__global__ void conv_w(const float* __restrict__ W, int Nd)
{
    __shared__ float t[32][33];
    __half* dst = SEL ? g_Wp : g_Wq;
    int n0 = blockIdx.x * 32, k0 = blockIdx.y * 32;
    #pragma unroll
    for (int i = 0; i < 4; i++) {
        int k = k0 + threadIdx.y + i * 8;
        t[threadIdx.y + i * 8][threadIdx.x] = W[(size_t)k * Nd + n0 + threadIdx.x];
    }
    __syncthreads();
    #pragma unroll
    for (int i = 0; i < 4; i++) {
        int n = n0 + threadIdx.y + i * 8;
        int k = k0 + threadIdx.x;
        dst[(size_t)n * KDIM + k] = __float2half_rn(t[threadIdx.x][threadIdx.y + i * 8]);
    }
}

// ---------------- fp16 GEMM on mma.sync (128x128 tile, warp 64x32) ----------------
// Round-11 proven configuration: BK=32, fragment-phase grouping, 2 CTAs/SM.
// MODE 0: QKV — A = g_Ah, B = g_Wq, epilogue scatter to Q/K/V.
// MODE 1: proj — A = g_Oh, B = g_Wp, out fp32 + bias.
template <int MODE>
__global__ __launch_bounds__(256, 2)
void gemm_fp16(const float* __restrict__ bias, float* __restrict__ out)
{
    constexpr int NCH = (MODE == 0) ? NCHUNK_QKV : NCHUNK_PROJ;
    __shared__ __align__(16) __half As[2][128 * PADK];
    __shared__ __align__(16) __half Bs[2][128 * PADK];

    const int tid = threadIdx.x;
    const int lane = tid & 31, wid = tid >> 5;
    const int warp_m = wid >> 2, warp_n = wid & 3;
    const int mTile = blockIdx.y, nTile = blockIdx.x;
    const int aRow0 = mTile * 128, bRow0 = nTile * 128;
    const int lrow = tid >> 2, lseg = tid & 3;

    const uint32_t asBase = smem_u32(&As[0][0]);
    const uint32_t bsBase = smem_u32(&Bs[0][0]);
    const uint32_t stageBytes = 128 * PADK * 2;

    auto load_chunk = [&](int kc) {
        int k0 = kc * BK;
        const __half* Ap = (MODE == 0) ? g_Ah : g_Oh;
        const __half* Bp = (MODE == 0) ? g_Wq : g_Wp;
        uint32_t so = (uint32_t)(kc & 1) * stageBytes;
        #pragma unroll
        for (int i = 0; i < 2; i++) {
            int row = lrow + 64 * i;
            uint32_t doff = so + (uint32_t)row * (PADK * 2) + (uint32_t)lseg * 16;
            cp16(asBase + doff, Ap + (size_t)(aRow0 + row) * KDIM + k0 + lseg * 8);
            cp16(bsBase + doff, Bp + (size_t)(bRow0 + row) * KDIM + k0 + lseg * 8);
        }
        cp_commit();
    };

    float acc[4][4][4];
    #pragma unroll
    for (int mi = 0; mi < 4; mi++)
        #pragma unroll
        for (int ni = 0; ni < 4; ni++)
            #pragma unroll
            for (int q = 0; q < 4; q++) acc[mi][ni][q] = 0.0f;

    load_chunk(0);
    load_chunk(1);

    const int aRowL = warp_m * 64 + (lane & 15);
    const int aKoff = (lane >> 4) << 3;
    const int bRowL = warp_n * 32 + ((lane >> 4) << 3) + (lane & 7);
    const int bKoff = ((lane >> 3) & 1) << 3;

    #pragma unroll 1
    for (int kc = 0; kc < NCH; ++kc) {
        if (kc == NCH - 1) asm volatile("cp.async.wait_group 0;" ::: "memory");
        else               asm volatile("cp.async.wait_group 1;" ::: "memory");
        __syncthreads();

        uint32_t ab = asBase + (uint32_t)(kc & 1) * stageBytes;
        uint32_t bb = bsBase + (uint32_t)(kc & 1) * stageBytes;

        // phase 1: all fragment loads
        uint32_t a_r[2][4][4];
        uint32_t b_r[2][4][2];
        #pragma unroll
        for (int ks = 0; ks < 2; ks++) {
            #pragma unroll
            for (int mi = 0; mi < 4; mi++)
                ldm_x4(a_r[ks][mi], ab + (uint32_t)(aRowL + mi * 16) * (PADK * 2)
                                      + (uint32_t)(ks * 16 + aKoff) * 2);
            #pragma unroll
            for (int np = 0; np < 2; np++) {
                uint32_t r[4];
                ldm_x4(r, bb + (uint32_t)(bRowL + np * 16) * (PADK * 2)
                            + (uint32_t)(ks * 16 + bKoff) * 2);
                b_r[ks][np*2][0] = r[0]; b_r[ks][np*2][1] = r[1];
                b_r[ks][np*2+1][0] = r[2]; b_r[ks][np*2+1][1] = r[3];
            }
        }
        // phase 2: all mma
        #pragma unroll
        for (int ks = 0; ks < 2; ks++)
            #pragma unroll
            for (int mi = 0; mi < 4; mi++)
                #pragma unroll
                for (int ni = 0; ni < 4; ni++)
                    mma_fp(acc[mi][ni], a_r[ks][mi], b_r[ks][ni]);

        __syncthreads();
        if (kc + 2 < NCH) load_chunk(kc + 2);
    }

    const int mBase = mTile * 128 + warp_m * 64;
    const int nBase = nTile * 128 + warp_n * 32;
    const int rq = lane >> 2, cq = (lane & 3) * 2;

    if (MODE == 0) {
        const int part = (nTile * 128) >> 10;   // 0=Q, 1=K, 2=V
        #pragma unroll
        for (int mi = 0; mi < 4; mi++)
            #pragma unroll
            for (int ni = 0; ni < 4; ni++) {
                int col = nBase + ni * 8 + cq;
                float2 bv = *(const float2*)&bias[col];
                int h = (col & 1023) >> 6, d = col & 63;
                #pragma unroll
                for (int h2 = 0; h2 < 2; h2++) {
                    int row = mBase + mi * 16 + rq + h2 * 8;
                    int b = row >> 11, n = row & 2047;
                    size_t idx = (((size_t)(b * NH + h)) * SEQ + n) * HD + d;
                    float v0 = acc[mi][ni][h2*2]   + bv.x;
                    float v1 = acc[mi][ni][h2*2+1] + bv.y;
                    if (part == 0)      store_h2(g_Qh, idx, v0 * QSCALE, v1 * QSCALE);
                    else if (part == 1) store_h2(g_Kh, idx, v0, v1);
                    else                store_h2(g_Vh, idx, v0, v1);
                }
            }
    } else {
        #pragma unroll
        for (int mi = 0; mi < 4; mi++)
            #pragma unroll
            for (int ni = 0; ni < 4; ni++) {
                int col = nBase + ni * 8 + cq;
                float2 bv = *(const float2*)&bias[col];
                #pragma unroll
                for (int h2 = 0; h2 < 2; h2++) {
                    int row = mBase + mi * 16 + rq + h2 * 8;
                    float2 v = make_float2(acc[mi][ni][h2*2] + bv.x,
                                           acc[mi][ni][h2*2+1] + bv.y);
                    *(float2*)&out[(size_t)row * CDIM + col] = v;
                }
            }
    }
}

// ---------------- tensor-core flash attention: fp16 QK, fp16 single-term PV ------
__global__ __launch_bounds__(128)
void attn_mma()
{
    extern __shared__ char sm_[];
    const int tid  = threadIdx.x;
    const int lane = tid & 31, wid = tid >> 5;
    const int bh = blockIdx.y, qt = blockIdx.x;
    const int b = bh >> 4, h = bh & 15;

    const uint32_t QS  = smem_u32(sm_);
    const uint32_t KV0 = QS + QSMEM_BYTES;
    const size_t ghead = (size_t)bh * SEQ * HD;

    {   // Q tile: 128 rows x 64 fp16
        const __half* qs = g_Qh + ghead + ((size_t)qt * 128 + tid) * HD;
        uint32_t dst = QS + (uint32_t)tid * QROWB;
        #pragma unroll
        for (int s = 0; s < 8; s++) cp16(dst + s*16, qs + s*8);
        cp_commit();
    }

    auto load_kv = [&](int kt) {
        int r = tid >> 1, half = tid & 1;
        const size_t grow = ghead + ((size_t)kt * 64 + r) * HD + half * 32;
        const uint32_t base = KV0 + (uint32_t)(kt & 1) * KVBUF;
        uint32_t kdst = base + (uint32_t)r * KROWB + (uint32_t)half * 64;
        const __half* ks = g_Kh + grow;
        #pragma unroll
        for (int i = 0; i < 4; i++) cp16(kdst + i*16, ks + i*8);
        uint32_t vdst = base + KTILE + (uint32_t)r * VROWB + (uint32_t)half * 64;
        const __half* vs = g_Vh + grow;
        #pragma unroll
        for (int i = 0; i < 4; i++) cp16(vdst + i*16, vs + i*8);
        cp_commit();
    };
    load_kv(0);
    load_kv(1);

    asm volatile("cp.async.wait_group 2;" ::: "memory");
    __syncthreads();

    const int wrow = wid * 32;
    uint32_t qf[2][4][4];
    #pragma unroll
    for (int mi = 0; mi < 2; mi++) {
        uint32_t rowa = QS + (uint32_t)(wrow + mi*16 + (lane & 15)) * QROWB
                      + (uint32_t)((lane >> 4) << 4);
        #pragma unroll
        for (int k = 0; k < 4; k++) ldm_x4(qf[mi][k], rowa + k*32);
    }

    float oc[2][8][4];
    #pragma unroll
    for (int mi = 0; mi < 2; mi++)
        #pragma unroll
        for (int n = 0; n < 8; n++)
            #pragma unroll
            for (int q = 0; q < 4; q++) oc[mi][n][q] = 0.0f;
    ull lacc[2][2];
    lacc[0][0] = lacc[0][1] = lacc[1][0] = lacc[1][1] = pack2(0.0f, 0.0f);

    #pragma unroll 1
    for (int kt = 0; kt < SEQ/64; ++kt) {
        asm volatile("cp.async.wait_group 1;" ::: "memory");
        __syncthreads();

        const uint32_t Kb = KV0 + (uint32_t)(kt & 1) * KVBUF;
        const uint32_t Vb = Kb + KTILE;

        float sc[2][8][4];
        #pragma unroll
        for (int mi = 0; mi < 2; mi++)
            #pragma unroll
            for (int n = 0; n < 8; n++)
                #pragma unroll
                for (int q = 0; q < 4; q++) sc[mi][n][q] = 0.0f;

        #pragma unroll
        for (int kk = 0; kk < 4; kk++) {
            uint32_t br[4][4];
            #pragma unroll
            for (int np = 0; np < 4; np++)
                ldm_x4(br[np], Kb + (uint32_t)(np*16 + ((lane >> 4) << 3) + (lane & 7)) * KROWB
                                 + (uint32_t)(kk*16 + (((lane >> 3) & 1) << 3)) * 2);
            #pragma unroll
            for (int mi = 0; mi < 2; mi++) {
                #pragma unroll
                for (int np = 0; np < 4; np++) {
                    mma_fp(sc[mi][np*2],   qf[mi][kk], &br[np][0]);
                    mma_fp(sc[mi][np*2+1], qf[mi][kk], &br[np][2]);
                }
            }
        }

        // exp2 -> P (single fp16) -> PV (single term)
        #pragma unroll
        for (int kk = 0; kk < 4; kk++) {
            uint32_t aP[2][4];
            #pragma unroll
            for (int mi = 0; mi < 2; mi++) {
                #pragma unroll
                for (int half = 0; half < 2; half++) {
                    int n = 2*kk + half;
                    ull p01 = exp2pair(pack2(sc[mi][n][0], sc[mi][n][1]));
                    ull p23 = exp2pair(pack2(sc[mi][n][2], sc[mi][n][3]));
                    lacc[mi][0] = add2(lacc[mi][0], p01);
                    lacc[mi][1] = add2(lacc[mi][1], p23);
                    aP[mi][half*2]   = h2pack(unpack2(p01));
                    aP[mi][half*2+1] = h2pack(unpack2(p23));
                }
            }
            const uint32_t krow = (uint32_t)(kk*16 + ((lane >> 3) & 1) * 8 + (lane & 7));
            #pragma unroll
            for (int nb = 0; nb < 4; nb++) {
                uint32_t bv[4];
                ldm_x4_t(bv, Vb + krow * VROWB + (uint32_t)(nb*16 + ((lane >> 4) << 3)) * 2);
                #pragma unroll
                for (int mi = 0; mi < 2; mi++) {
                    mma_fp(oc[mi][nb*2],   aP[mi], &bv[0]);
                    mma_fp(oc[mi][nb*2+1], aP[mi], &bv[2]);
                }
            }
        }
        __syncthreads();
        if (kt + 2 < SEQ/64) load_kv(kt + 2);
    }

    // normalize + single-fp16 write to [B,N,H*D]
    #pragma unroll
    for (int mi = 0; mi < 2; mi++) {
        float2 L0 = unpack2(lacc[mi][0]);
        float l0 = L0.x + L0.y;
        l0 += __shfl_xor_sync(0xFFFFFFFFu, l0, 1);
        l0 += __shfl_xor_sync(0xFFFFFFFFu, l0, 2);
        float2 L1 = unpack2(lacc[mi][1]);
        float l1 = L1.x + L1.y;
        l1 += __shfl_xor_sync(0xFFFFFFFFu, l1, 1);
        l1 += __shfl_xor_sync(0xFFFFFFFFu, l1, 2);
        float inv0 = 1.0f / l0, inv1 = 1.0f / l1;
        int r0 = qt * 128 + wrow + mi*16 + (lane >> 2);
        #pragma unroll
        for (int ni = 0; ni < 8; ni++) {
            int d = ni*8 + (lane & 3)*2;
            size_t i0 = ((size_t)(b * SEQ + r0)) * CDIM + h * HD + d;
            size_t i1 = ((size_t)(b * SEQ + r0 + 8)) * CDIM + h * HD + d;
            store_h2(g_Oh, i0, oc[mi][ni][0]*inv0, oc[mi][ni][1]*inv0);
            store_h2(g_Oh, i1, oc[mi][ni][2]*inv1, oc[mi][ni][3]*inv1);
        }
    }
}

// ---------------- launch ----------------
extern "C" void kernel_launch(void* const* d_in, const int* in_sizes, int n_in,
                              void* d_out, int out_size)
{
    const float* x      = (const float*)d_in[0];
    const float* W_qkv  = (const float*)d_in[1];
    const float* b_qkv  = (const float*)d_in[2];
    const float* W_proj = (const float*)d_in[3];
    const float* b_proj = (const float*)d_in[4];
    float* out = (float*)d_out;

    cudaFuncSetAttribute(attn_mma, cudaFuncAttributeMaxDynamicSharedMemorySize, ATTN_SMEM);

    conv_x<<<(MROWS * KDIM / 4 + 255) / 256, 256>>>(x, MROWS * KDIM / 4);
    {
        dim3 bdim(32, 8);
        dim3 gq(NQKV / 32, KDIM / 32);
        conv_w<0><<<gq, bdim>>>(W_qkv, NQKV);
        dim3 gp(CDIM / 32, KDIM / 32);
        conv_w<1><<<gp, bdim>>>(W_proj, CDIM);
    }
    {
        dim3 g(NQKV / 128, MROWS / 128);
        gemm_fp16<0><<<g, 256>>>(b_qkv, nullptr);
    }
    {
        dim3 ga(SEQ / 128, BB * NH);
        attn_mma<<<ga, 128, ATTN_SMEM>>>();
    }
    {
        dim3 g(CDIM / 128, MROWS / 128);
        gemm_fp16<1><<<g, 256>>>(b_proj, out);
    }
}

// round 14
// speedup vs baseline: 1.2637x; 1.1099x over previous
#include <cuda_runtime.h>
#include <cuda_fp16.h>
#include <cstdint>
#include <math.h>

#define BB   4
#define SEQ  2048
#define CDIM 1024
#define NH   16
#define HD   64
#define MROWS (BB*SEQ)
#define KDIM 1024
#define NQKV 3072
#define BK   32
#define PADK 40
#define NCHUNK_QKV 32          // K' = 1024/32 (single fp16 term)
#define NCHUNK_PROJ 32

#define GEMM_STAGE (128*PADK*2)            // 10240 B per operand per stage
#define GEMM_SMEM  (6*GEMM_STAGE)          // 61440 B: A x3 stages, B x3 stages

// attention smem geometry (3 KV stages)
#define QROWB 144
#define QSMEM_BYTES (128*QROWB)            // 18432
#define KROWB 144
#define KTILE (64*KROWB)                   // 9216
#define VROWB 144
#define VTILE (64*VROWB)                   // 9216
#define KVBUF (KTILE+VTILE)                // 18432
#define ATTN_SMEM (QSMEM_BYTES + 3*KVBUF)  // 73728

#define QSCALE 0.1803368801111179f         // 0.125 * log2(e)

// ---------------- scratch ----------------
__device__ __half g_Qh[BB*NH*SEQ*HD];      // [B,H,N,D] fp16, pre-scaled
__device__ __half g_Kh[BB*NH*SEQ*HD];
__device__ __half g_Vh[BB*NH*SEQ*HD];
__device__ __half g_Ah[MROWS*KDIM];        // x single fp16
__device__ __half g_Wq[NQKV*KDIM];         // W_qkv^T single fp16 [N,K]
__device__ __half g_Oh[MROWS*CDIM];        // attention out single fp16 [B,N,H*D]
__device__ __half g_Wp[CDIM*KDIM];         // W_proj^T single fp16 [N,K]

// ---------------- helpers ----------------
typedef unsigned long long ull;

__device__ __forceinline__ uint32_t smem_u32(const void* p) {
    return (uint32_t)__cvta_generic_to_shared(p);
}
__device__ __forceinline__ ull ffma2(ull a, ull b, ull c) {
    ull d; asm("fma.rn.f32x2 %0, %1, %2, %3;" : "=l"(d) : "l"(a), "l"(b), "l"(c)); return d;
}
__device__ __forceinline__ ull add2(ull a, ull b) {
    ull d; asm("add.rn.f32x2 %0, %1, %2;" : "=l"(d) : "l"(a), "l"(b)); return d;
}
__device__ __forceinline__ ull pack2(float lo, float hi) {
    ull r; asm("mov.b64 %0, {%1, %2};" : "=l"(r) : "f"(lo), "f"(hi)); return r;
}
__device__ __forceinline__ float2 unpack2(ull v) {
    float lo, hi; asm("mov.b64 {%0, %1}, %2;" : "=f"(lo), "=f"(hi) : "l"(v));
    return make_float2(lo, hi);
}
__device__ __forceinline__ void cp16(uint32_t dst, const void* src) {
    asm volatile("cp.async.cg.shared.global [%0], [%1], 16;" :: "r"(dst), "l"(src));
}
__device__ __forceinline__ void cp_commit() { asm volatile("cp.async.commit_group;"); }
__device__ __forceinline__ void ldm_x4(uint32_t* r, uint32_t addr) {
    asm volatile("ldmatrix.sync.aligned.m8n8.x4.shared.b16 {%0,%1,%2,%3}, [%4];"
                 : "=r"(r[0]), "=r"(r[1]), "=r"(r[2]), "=r"(r[3]) : "r"(addr));
}
__device__ __forceinline__ void ldm_x4_t(uint32_t* r, uint32_t addr) {
    asm volatile("ldmatrix.sync.aligned.m8n8.x4.trans.shared.b16 {%0,%1,%2,%3}, [%4];"
                 : "=r"(r[0]), "=r"(r[1]), "=r"(r[2]), "=r"(r[3]) : "r"(addr));
}
__device__ __forceinline__ void mma_fp(float* c, const uint32_t* a, const uint32_t* b) {
    asm volatile(
        "mma.sync.aligned.m16n8k16.row.col.f32.f16.f16.f32 "
        "{%0,%1,%2,%3}, {%4,%5,%6,%7}, {%8,%9}, {%0,%1,%2,%3};"
        : "+f"(c[0]), "+f"(c[1]), "+f"(c[2]), "+f"(c[3])
        : "r"(a[0]), "r"(a[1]), "r"(a[2]), "r"(a[3]), "r"(b[0]), "r"(b[1]));
}
__device__ __forceinline__ void store_h2(__half* A, size_t idx, float v0, float v1) {
    uint32_t r; asm("cvt.rn.f16x2.f32 %0, %1, %2;" : "=r"(r) : "f"(v1), "f"(v0));
    *(uint32_t*)&A[idx] = r;
}
__device__ __forceinline__ uint32_t h2pack(float2 v) {
    uint32_t r; asm("cvt.rn.f16x2.f32 %0, %1, %2;" : "=r"(r) : "f"(v.y), "f"(v.x));
    return r;
}

#define MAGICF 12582912.0f
// degree-4 2^f poly on f in [-0.5, 0.5]; max rel err ~1e-6
__device__ __forceinline__ ull exp2pair(ull t) {
    const ull MAGIC2  = pack2(MAGICF, MAGICF);
    const ull NMAGIC2 = pack2(-MAGICF, -MAGICF);
    const ull NONE2   = pack2(-1.0f, -1.0f);
    const ull ONE2    = pack2(1.0f, 1.0f);
    const ull C1 = pack2(0.6931471971938464f, 0.6931471971938464f);
    const ull C2 = pack2(0.2402264689063408f, 0.2402264689063408f);
    const ull C3 = pack2(0.0555042108516768f, 0.0555042108516768f);
    const ull C4 = pack2(0.0096181289721693f, 0.0096181289721693f);
    ull m = add2(t, MAGIC2);
    ull kf = add2(m, NMAGIC2);
    ull f = ffma2(kf, NONE2, t);
    ull p = ffma2(C4, f, C3);
    p = ffma2(p, f, C2); p = ffma2(p, f, C1); p = ffma2(p, f, ONE2);
    float2 mf = unpack2(m); float2 pf = unpack2(p);
    uint32_t r0 = __float_as_uint(pf.x) + (__float_as_uint(mf.x) << 23);
    uint32_t r1 = __float_as_uint(pf.y) + (__float_as_uint(mf.y) << 23);
    return pack2(__uint_as_float(r0), __uint_as_float(r1));
}

// ---------------- conversion kernels ----------------
__global__ void conv_x(const float* __restrict__ src, int n4)
{
    int i = blockIdx.x * blockDim.x + threadIdx.x;
    if (i >= n4) return;
    float4 v = ((const float4*)src)[i];
    union { uint2 u; __half h[4]; } ph;
    ph.h[0] = __float2half_rn(v.x);
    ph.h[1] = __float2half_rn(v.y);
    ph.h[2] = __float2half_rn(v.z);
    ph.h[3] = __float2half_rn(v.w);
    ((uint2*)g_Ah)[i] = ph.u;
}

template <int SEL>
__global__ void conv_w(const float* __restrict__ W, int Nd)
{
    __shared__ float t[32][33];
    __half* dst = SEL ? g_Wp : g_Wq;
    int n0 = blockIdx.x * 32, k0 = blockIdx.y * 32;
    #pragma unroll
    for (int i = 0; i < 4; i++) {
        int k = k0 + threadIdx.y + i * 8;
        t[threadIdx.y + i * 8][threadIdx.x] = W[(size_t)k * Nd + n0 + threadIdx.x];
    }
    __syncthreads();
    #pragma unroll
    for (int i = 0; i < 4; i++) {
        int n = n0 + threadIdx.y + i * 8;
        int k = k0 + threadIdx.x;
        dst[(size_t)n * KDIM + k] = __float2half_rn(t[threadIdx.x][threadIdx.y + i * 8]);
    }
}

// ---------------- fp16 GEMM: 128x128 tile, warp 64x32, 3-stage single-sync ----
template <int MODE>
__global__ __launch_bounds__(256, 2)
void gemm_fp16(const float* __restrict__ bias, float* __restrict__ out)
{
    constexpr int NCH = (MODE == 0) ? NCHUNK_QKV : NCHUNK_PROJ;
    extern __shared__ char gsm[];

    const int tid = threadIdx.x;
    const int lane = tid & 31, wid = tid >> 5;
    const int warp_m = wid >> 2, warp_n = wid & 3;
    const int mTile = blockIdx.y, nTile = blockIdx.x;
    const int aRow0 = mTile * 128, bRow0 = nTile * 128;
    const int lrow = tid >> 2, lseg = tid & 3;

    const uint32_t asBase = smem_u32(gsm);
    const uint32_t bsBase = asBase + 3 * GEMM_STAGE;

    auto load_chunk = [&](int kc) {
        int k0 = kc * BK;
        const __half* Ap = (MODE == 0) ? g_Ah : g_Oh;
        const __half* Bp = (MODE == 0) ? g_Wq : g_Wp;
        uint32_t so = (uint32_t)(kc % 3) * GEMM_STAGE;
        #pragma unroll
        for (int i = 0; i < 2; i++) {
            int row = lrow + 64 * i;
            uint32_t doff = so + (uint32_t)row * (PADK * 2) + (uint32_t)lseg * 16;
            cp16(asBase + doff, Ap + (size_t)(aRow0 + row) * KDIM + k0 + lseg * 8);
            cp16(bsBase + doff, Bp + (size_t)(bRow0 + row) * KDIM + k0 + lseg * 8);
        }
        cp_commit();
    };

    float acc[4][4][4];
    #pragma unroll
    for (int mi = 0; mi < 4; mi++)
        #pragma unroll
        for (int ni = 0; ni < 4; ni++)
            #pragma unroll
            for (int q = 0; q < 4; q++) acc[mi][ni][q] = 0.0f;

    load_chunk(0);
    load_chunk(1);

    const int aRowL = warp_m * 64 + (lane & 15);
    const int aKoff = (lane >> 4) << 3;
    const int bRowL = warp_n * 32 + ((lane >> 4) << 3) + (lane & 7);
    const int bKoff = ((lane >> 3) & 1) << 3;

    #pragma unroll 1
    for (int kc = 0; kc < NCH; ++kc) {
        if (kc >= NCH - 2) asm volatile("cp.async.wait_group 0;" ::: "memory");
        else               asm volatile("cp.async.wait_group 1;" ::: "memory");
        __syncthreads();   // single barrier per chunk: orders stage reuse AND data ready

        uint32_t ab = asBase + (uint32_t)(kc % 3) * GEMM_STAGE;
        uint32_t bb = bsBase + (uint32_t)(kc % 3) * GEMM_STAGE;

        // phase 1: all fragment loads
        uint32_t a_r[2][4][4];
        uint32_t b_r[2][4][2];
        #pragma unroll
        for (int ks = 0; ks < 2; ks++) {
            #pragma unroll
            for (int mi = 0; mi < 4; mi++)
                ldm_x4(a_r[ks][mi], ab + (uint32_t)(aRowL + mi * 16) * (PADK * 2)
                                      + (uint32_t)(ks * 16 + aKoff) * 2);
            #pragma unroll
            for (int np = 0; np < 2; np++) {
                uint32_t r[4];
                ldm_x4(r, bb + (uint32_t)(bRowL + np * 16) * (PADK * 2)
                            + (uint32_t)(ks * 16 + bKoff) * 2);
                b_r[ks][np*2][0] = r[0]; b_r[ks][np*2][1] = r[1];
                b_r[ks][np*2+1][0] = r[2]; b_r[ks][np*2+1][1] = r[3];
            }
        }
        // prefetch into stage (kc+2)%3 = (kc-1)%3, consumed at kc-1; safe past the sync
        if (kc + 2 < NCH) load_chunk(kc + 2);

        // phase 2: all mma
        #pragma unroll
        for (int ks = 0; ks < 2; ks++)
            #pragma unroll
            for (int mi = 0; mi < 4; mi++)
                #pragma unroll
                for (int ni = 0; ni < 4; ni++)
                    mma_fp(acc[mi][ni], a_r[ks][mi], b_r[ks][ni]);
    }

    const int mBase = mTile * 128 + warp_m * 64;
    const int nBase = nTile * 128 + warp_n * 32;
    const int rq = lane >> 2, cq = (lane & 3) * 2;

    if (MODE == 0) {
        const int part = (nTile * 128) >> 10;   // 0=Q, 1=K, 2=V
        #pragma unroll
        for (int mi = 0; mi < 4; mi++)
            #pragma unroll
            for (int ni = 0; ni < 4; ni++) {
                int col = nBase + ni * 8 + cq;
                float2 bv = *(const float2*)&bias[col];
                int h = (col & 1023) >> 6, d = col & 63;
                #pragma unroll
                for (int h2 = 0; h2 < 2; h2++) {
                    int row = mBase + mi * 16 + rq + h2 * 8;
                    int b = row >> 11, n = row & 2047;
                    size_t idx = (((size_t)(b * NH + h)) * SEQ + n) * HD + d;
                    float v0 = acc[mi][ni][h2*2]   + bv.x;
                    float v1 = acc[mi][ni][h2*2+1] + bv.y;
                    if (part == 0)      store_h2(g_Qh, idx, v0 * QSCALE, v1 * QSCALE);
                    else if (part == 1) store_h2(g_Kh, idx, v0, v1);
                    else                store_h2(g_Vh, idx, v0, v1);
                }
            }
    } else {
        #pragma unroll
        for (int mi = 0; mi < 4; mi++)
            #pragma unroll
            for (int ni = 0; ni < 4; ni++) {
                int col = nBase + ni * 8 + cq;
                float2 bv = *(const float2*)&bias[col];
                #pragma unroll
                for (int h2 = 0; h2 < 2; h2++) {
                    int row = mBase + mi * 16 + rq + h2 * 8;
                    float2 v = make_float2(acc[mi][ni][h2*2] + bv.x,
                                           acc[mi][ni][h2*2+1] + bv.y);
                    *(float2*)&out[(size_t)row * CDIM + col] = v;
                }
            }
    }
}

// ---------------- flash attention: fp16 QK, single-term PV, 3-stage single-sync --
__global__ __launch_bounds__(128)
void attn_mma()
{
    extern __shared__ char sm_[];
    const int tid  = threadIdx.x;
    const int lane = tid & 31, wid = tid >> 5;
    const int bh = blockIdx.y, qt = blockIdx.x;
    const int b = bh >> 4, h = bh & 15;
    constexpr int NT = SEQ / 64;

    const uint32_t QS  = smem_u32(sm_);
    const uint32_t KV0 = QS + QSMEM_BYTES;
    const size_t ghead = (size_t)bh * SEQ * HD;

    {   // Q tile: 128 rows x 64 fp16
        const __half* qs = g_Qh + ghead + ((size_t)qt * 128 + tid) * HD;
        uint32_t dst = QS + (uint32_t)tid * QROWB;
        #pragma unroll
        for (int s = 0; s < 8; s++) cp16(dst + s*16, qs + s*8);
        cp_commit();
    }

    auto load_kv = [&](int kt) {
        int r = tid >> 1, half = tid & 1;
        const size_t grow = ghead + ((size_t)kt * 64 + r) * HD + half * 32;
        const uint32_t base = KV0 + (uint32_t)(kt % 3) * KVBUF;
        uint32_t kdst = base + (uint32_t)r * KROWB + (uint32_t)half * 64;
        const __half* ks = g_Kh + grow;
        #pragma unroll
        for (int i = 0; i < 4; i++) cp16(kdst + i*16, ks + i*8);
        uint32_t vdst = base + KTILE + (uint32_t)r * VROWB + (uint32_t)half * 64;
        const __half* vs = g_Vh + grow;
        #pragma unroll
        for (int i = 0; i < 4; i++) cp16(vdst + i*16, vs + i*8);
        cp_commit();
    };
    load_kv(0);
    load_kv(1);

    asm volatile("cp.async.wait_group 2;" ::: "memory");   // Q ready
    __syncthreads();

    const int wrow = wid * 32;
    uint32_t qf[2][4][4];
    #pragma unroll
    for (int mi = 0; mi < 2; mi++) {
        uint32_t rowa = QS + (uint32_t)(wrow + mi*16 + (lane & 15)) * QROWB
                      + (uint32_t)((lane >> 4) << 4);
        #pragma unroll
        for (int k = 0; k < 4; k++) ldm_x4(qf[mi][k], rowa + k*32);
    }

    float oc[2][8][4];
    #pragma unroll
    for (int mi = 0; mi < 2; mi++)
        #pragma unroll
        for (int n = 0; n < 8; n++)
            #pragma unroll
            for (int q = 0; q < 4; q++) oc[mi][n][q] = 0.0f;
    ull lacc[2][2];
    lacc[0][0] = lacc[0][1] = lacc[1][0] = lacc[1][1] = pack2(0.0f, 0.0f);

    #pragma unroll 1
    for (int kt = 0; kt < NT; ++kt) {
        if (kt >= NT - 2) asm volatile("cp.async.wait_group 0;" ::: "memory");
        else              asm volatile("cp.async.wait_group 1;" ::: "memory");
        __syncthreads();   // single barrier per tile

        const uint32_t Kb = KV0 + (uint32_t)(kt % 3) * KVBUF;
        const uint32_t Vb = Kb + KTILE;

        float sc[2][8][4];
        #pragma unroll
        for (int mi = 0; mi < 2; mi++)
            #pragma unroll
            for (int n = 0; n < 8; n++)
                #pragma unroll
                for (int q = 0; q < 4; q++) sc[mi][n][q] = 0.0f;

        #pragma unroll
        for (int kk = 0; kk < 4; kk++) {
            uint32_t br[4][4];
            #pragma unroll
            for (int np = 0; np < 4; np++)
                ldm_x4(br[np], Kb + (uint32_t)(np*16 + ((lane >> 4) << 3) + (lane & 7)) * KROWB
                                 + (uint32_t)(kk*16 + (((lane >> 3) & 1) << 3)) * 2);
            #pragma unroll
            for (int mi = 0; mi < 2; mi++) {
                #pragma unroll
                for (int np = 0; np < 4; np++) {
                    mma_fp(sc[mi][np*2],   qf[mi][kk], &br[np][0]);
                    mma_fp(sc[mi][np*2+1], qf[mi][kk], &br[np][2]);
                }
            }
        }

        // prefetch into stage (kt+2)%3 = (kt-1)%3, consumed at kt-1; safe past the sync
        if (kt + 2 < NT) load_kv(kt + 2);

        // exp2 -> P (single fp16) -> PV (single term)
        #pragma unroll
        for (int kk = 0; kk < 4; kk++) {
            uint32_t aP[2][4];
            #pragma unroll
            for (int mi = 0; mi < 2; mi++) {
                #pragma unroll
                for (int half = 0; half < 2; half++) {
                    int n = 2*kk + half;
                    ull p01 = exp2pair(pack2(sc[mi][n][0], sc[mi][n][1]));
                    ull p23 = exp2pair(pack2(sc[mi][n][2], sc[mi][n][3]));
                    lacc[mi][0] = add2(lacc[mi][0], p01);
                    lacc[mi][1] = add2(lacc[mi][1], p23);
                    aP[mi][half*2]   = h2pack(unpack2(p01));
                    aP[mi][half*2+1] = h2pack(unpack2(p23));
                }
            }
            const uint32_t krow = (uint32_t)(kk*16 + ((lane >> 3) & 1) * 8 + (lane & 7));
            #pragma unroll
            for (int nb = 0; nb < 4; nb++) {
                uint32_t bv[4];
                ldm_x4_t(bv, Vb + krow * VROWB + (uint32_t)(nb*16 + ((lane >> 4) << 3)) * 2);
                #pragma unroll
                for (int mi = 0; mi < 2; mi++) {
                    mma_fp(oc[mi][nb*2],   aP[mi], &bv[0]);
                    mma_fp(oc[mi][nb*2+1], aP[mi], &bv[2]);
                }
            }
        }
    }

    // normalize + single-fp16 write to [B,N,H*D]
    #pragma unroll
    for (int mi = 0; mi < 2; mi++) {
        float2 L0 = unpack2(lacc[mi][0]);
        float l0 = L0.x + L0.y;
        l0 += __shfl_xor_sync(0xFFFFFFFFu, l0, 1);
        l0 += __shfl_xor_sync(0xFFFFFFFFu, l0, 2);
        float2 L1 = unpack2(lacc[mi][1]);
        float l1 = L1.x + L1.y;
        l1 += __shfl_xor_sync(0xFFFFFFFFu, l1, 1);
        l1 += __shfl_xor_sync(0xFFFFFFFFu, l1, 2);
        float inv0 = 1.0f / l0, inv1 = 1.0f / l1;
        int r0 = qt * 128 + wrow + mi*16 + (lane >> 2);
        #pragma unroll
        for (int ni = 0; ni < 8; ni++) {
            int d = ni*8 + (lane & 3)*2;
            size_t i0 = ((size_t)(b * SEQ + r0)) * CDIM + h * HD + d;
            size_t i1 = ((size_t)(b * SEQ + r0 + 8)) * CDIM + h * HD + d;
            store_h2(g_Oh, i0, oc[mi][ni][0]*inv0, oc[mi][ni][1]*inv0);
            store_h2(g_Oh, i1, oc[mi][ni][2]*inv1, oc[mi][ni][3]*inv1);
        }
    }
}

// ---------------- launch ----------------
extern "C" void kernel_launch(void* const* d_in, const int* in_sizes, int n_in,
                              void* d_out, int out_size)
{
    const float* x      = (const float*)d_in[0];
    const float* W_qkv  = (const float*)d_in[1];
    const float* b_qkv  = (const float*)d_in[2];
    const float* W_proj = (const float*)d_in[3];
    const float* b_proj = (const float*)d_in[4];
    float* out = (float*)d_out;

    cudaFuncSetAttribute(attn_mma, cudaFuncAttributeMaxDynamicSharedMemorySize, ATTN_SMEM);
    cudaFuncSetAttribute(gemm_fp16<0>, cudaFuncAttributeMaxDynamicSharedMemorySize, GEMM_SMEM);
    cudaFuncSetAttribute(gemm_fp16<1>, cudaFuncAttributeMaxDynamicSharedMemorySize, GEMM_SMEM);

    conv_x<<<(MROWS * KDIM / 4 + 255) / 256, 256>>>(x, MROWS * KDIM / 4);
    {
        dim3 bdim(32, 8);
        dim3 gq(NQKV / 32, KDIM / 32);
        conv_w<0><<<gq, bdim>>>(W_qkv, NQKV);
        dim3 gp(CDIM / 32, KDIM / 32);
        conv_w<1><<<gp, bdim>>>(W_proj, CDIM);
    }
    {
        dim3 g(NQKV / 128, MROWS / 128);
        gemm_fp16<0><<<g, 256, GEMM_SMEM>>>(b_qkv, nullptr);
    }
    {
        dim3 ga(SEQ / 128, BB * NH);
        attn_mma<<<ga, 128, ATTN_SMEM>>>();
    }
    {
        dim3 g(CDIM / 128, MROWS / 128);
        gemm_fp16<1><<<g, 256, GEMM_SMEM>>>(b_proj, out);
    }
}

// round 15
// speedup vs baseline: 1.2639x; 1.0002x over previous
#include <cuda_runtime.h>
#include <cuda_fp16.h>
#include <cstdint>
#include <math.h>

#define BB   4
#define SEQ  2048
#define CDIM 1024
#define NH   16
#define HD   64
#define MROWS (BB*SEQ)
#define KDIM 1024
#define NQKV 3072
#define BK   32
#define PADK 40
#define NCHUNK_QKV 32          // K' = 1024/32 (single fp16 term)
#define NCHUNK_PROJ 32

#define GEMM_STAGE (128*PADK*2)            // 10240 B per operand per stage
#define GEMM_SMEM  (6*GEMM_STAGE)          // 61440 B: A x3 stages, B x3 stages

// attention smem geometry (3 KV stages)
#define QROWB 144
#define QSMEM_BYTES (128*QROWB)            // 18432
#define KROWB 144
#define KTILE (64*KROWB)                   // 9216
#define VROWB 144
#define VTILE (64*VROWB)                   // 9216
#define KVBUF (KTILE+VTILE)                // 18432
#define ATTN_SMEM (QSMEM_BYTES + 3*KVBUF)  // 73728

#define QSCALE 0.1803368801111179f         // 0.125 * log2(e)

// ---------------- scratch ----------------
__device__ __half g_Qh[BB*NH*SEQ*HD];      // [B,H,N,D] fp16, pre-scaled
__device__ __half g_Kh[BB*NH*SEQ*HD];
__device__ __half g_Vh[BB*NH*SEQ*HD];
__device__ __half g_Ah[MROWS*KDIM];        // x single fp16
__device__ __half g_Wq[NQKV*KDIM];         // W_qkv^T single fp16 [N,K]
__device__ __half g_Oh[MROWS*CDIM];        // attention out single fp16 [B,N,H*D]
__device__ __half g_Wp[CDIM*KDIM];         // W_proj^T single fp16 [N,K]

// ---------------- helpers ----------------
typedef unsigned long long ull;

__device__ __forceinline__ uint32_t smem_u32(const void* p) {
    return (uint32_t)__cvta_generic_to_shared(p);
}
__device__ __forceinline__ ull ffma2(ull a, ull b, ull c) {
    ull d; asm("fma.rn.f32x2 %0, %1, %2, %3;" : "=l"(d) : "l"(a), "l"(b), "l"(c)); return d;
}
__device__ __forceinline__ ull add2(ull a, ull b) {
    ull d; asm("add.rn.f32x2 %0, %1, %2;" : "=l"(d) : "l"(a), "l"(b)); return d;
}
__device__ __forceinline__ ull pack2(float lo, float hi) {
    ull r; asm("mov.b64 %0, {%1, %2};" : "=l"(r) : "f"(lo), "f"(hi)); return r;
}
__device__ __forceinline__ float2 unpack2(ull v) {
    float lo, hi; asm("mov.b64 {%0, %1}, %2;" : "=f"(lo), "=f"(hi) : "l"(v));
    return make_float2(lo, hi);
}
__device__ __forceinline__ void cp16(uint32_t dst, const void* src) {
    asm volatile("cp.async.cg.shared.global [%0], [%1], 16;" :: "r"(dst), "l"(src));
}
__device__ __forceinline__ void cp_commit() { asm volatile("cp.async.commit_group;"); }
__device__ __forceinline__ void ldm_x4(uint32_t* r, uint32_t addr) {
    asm volatile("ldmatrix.sync.aligned.m8n8.x4.shared.b16 {%0,%1,%2,%3}, [%4];"
                 : "=r"(r[0]), "=r"(r[1]), "=r"(r[2]), "=r"(r[3]) : "r"(addr));
}
__device__ __forceinline__ void ldm_x4_t(uint32_t* r, uint32_t addr) {
    asm volatile("ldmatrix.sync.aligned.m8n8.x4.trans.shared.b16 {%0,%1,%2,%3}, [%4];"
                 : "=r"(r[0]), "=r"(r[1]), "=r"(r[2]), "=r"(r[3]) : "r"(addr));
}
__device__ __forceinline__ void mma_fp(float* c, const uint32_t* a, const uint32_t* b) {
    asm volatile(
        "mma.sync.aligned.m16n8k16.row.col.f32.f16.f16.f32 "
        "{%0,%1,%2,%3}, {%4,%5,%6,%7}, {%8,%9}, {%0,%1,%2,%3};"
        : "+f"(c[0]), "+f"(c[1]), "+f"(c[2]), "+f"(c[3])
        : "r"(a[0]), "r"(a[1]), "r"(a[2]), "r"(a[3]), "r"(b[0]), "r"(b[1]));
}
__device__ __forceinline__ void store_h2(__half* A, size_t idx, float v0, float v1) {
    uint32_t r; asm("cvt.rn.f16x2.f32 %0, %1, %2;" : "=r"(r) : "f"(v1), "f"(v0));
    *(uint32_t*)&A[idx] = r;
}
__device__ __forceinline__ uint32_t h2pack(float2 v) {
    uint32_t r; asm("cvt.rn.f16x2.f32 %0, %1, %2;" : "=r"(r) : "f"(v.y), "f"(v.x));
    return r;
}

#define MAGICF 12582912.0f
// degree-4 2^f poly on f in [-0.5, 0.5]; max rel err ~1e-6
__device__ __forceinline__ ull exp2pair(ull t) {
    const ull MAGIC2  = pack2(MAGICF, MAGICF);
    const ull NMAGIC2 = pack2(-MAGICF, -MAGICF);
    const ull NONE2   = pack2(-1.0f, -1.0f);
    const ull ONE2    = pack2(1.0f, 1.0f);
    const ull C1 = pack2(0.6931471971938464f, 0.6931471971938464f);
    const ull C2 = pack2(0.2402264689063408f, 0.2402264689063408f);
    const ull C3 = pack2(0.0555042108516768f, 0.0555042108516768f);
    const ull C4 = pack2(0.0096181289721693f, 0.0096181289721693f);
    ull m = add2(t, MAGIC2);
    ull kf = add2(m, NMAGIC2);
    ull f = ffma2(kf, NONE2, t);
    ull p = ffma2(C4, f, C3);
    p = ffma2(p, f, C2); p = ffma2(p, f, C1); p = ffma2(p, f, ONE2);
    float2 mf = unpack2(m); float2 pf = unpack2(p);
    uint32_t r0 = __float_as_uint(pf.x) + (__float_as_uint(mf.x) << 23);
    uint32_t r1 = __float_as_uint(pf.y) + (__float_as_uint(mf.y) << 23);
    return pack2(__uint_as_float(r0), __uint_as_float(r1));
}

// ---------------- conversion kernels ----------------
__global__ void conv_x(const float* __restrict__ src, int n4)
{
    int i = blockIdx.x * blockDim.x + threadIdx.x;
    if (i >= n4) return;
    float4 v = ((const float4*)src)[i];
    union { uint2 u; __half h[4]; } ph;
    ph.h[0] = __float2half_rn(v.x);
    ph.h[1] = __float2half_rn(v.y);
    ph.h[2] = __float2half_rn(v.z);
    ph.h[3] = __float2half_rn(v.w);
    ((uint2*)g_Ah)[i] = ph.u;
}

template <int SEL>
__global__ void conv_w(const float* __restrict__ W, int Nd)
{
    __shared__ float t[32][33];
    __half* dst = SEL ? g_Wp : g_Wq;
    int n0 = blockIdx.x * 32, k0 = blockIdx.y * 32;
    #pragma unroll
    for (int i = 0; i < 4; i++) {
        int k = k0 + threadIdx.y + i * 8;
        t[threadIdx.y + i * 8][threadIdx.x] = W[(size_t)k * Nd + n0 + threadIdx.x];
    }
    __syncthreads();
    #pragma unroll
    for (int i = 0; i < 4; i++) {
        int n = n0 + threadIdx.y + i * 8;
        int k = k0 + threadIdx.x;
        dst[(size_t)n * KDIM + k] = __float2half_rn(t[threadIdx.x][threadIdx.y + i * 8]);
    }
}

// ---------------- fp16 GEMM: 128x128 tile, warp 64x32, 3-stage single-sync ----
template <int MODE>
__global__ __launch_bounds__(256, 2)
void gemm_fp16(const float* __restrict__ bias, float* __restrict__ out)
{
    constexpr int NCH = (MODE == 0) ? NCHUNK_QKV : NCHUNK_PROJ;
    extern __shared__ char gsm[];

    const int tid = threadIdx.x;
    const int lane = tid & 31, wid = tid >> 5;
    const int warp_m = wid >> 2, warp_n = wid & 3;
    const int mTile = blockIdx.y, nTile = blockIdx.x;
    const int aRow0 = mTile * 128, bRow0 = nTile * 128;
    const int lrow = tid >> 2, lseg = tid & 3;

    const uint32_t asBase = smem_u32(gsm);
    const uint32_t bsBase = asBase + 3 * GEMM_STAGE;

    auto load_chunk = [&](int kc) {
        int k0 = kc * BK;
        const __half* Ap = (MODE == 0) ? g_Ah : g_Oh;
        const __half* Bp = (MODE == 0) ? g_Wq : g_Wp;
        uint32_t so = (uint32_t)(kc % 3) * GEMM_STAGE;
        #pragma unroll
        for (int i = 0; i < 2; i++) {
            int row = lrow + 64 * i;
            uint32_t doff = so + (uint32_t)row * (PADK * 2) + (uint32_t)lseg * 16;
            cp16(asBase + doff, Ap + (size_t)(aRow0 + row) * KDIM + k0 + lseg * 8);
            cp16(bsBase + doff, Bp + (size_t)(bRow0 + row) * KDIM + k0 + lseg * 8);
        }
        cp_commit();
    };

    float acc[4][4][4];
    #pragma unroll
    for (int mi = 0; mi < 4; mi++)
        #pragma unroll
        for (int ni = 0; ni < 4; ni++)
            #pragma unroll
            for (int q = 0; q < 4; q++) acc[mi][ni][q] = 0.0f;

    load_chunk(0);
    load_chunk(1);

    const int aRowL = warp_m * 64 + (lane & 15);
    const int aKoff = (lane >> 4) << 3;
    const int bRowL = warp_n * 32 + ((lane >> 4) << 3) + (lane & 7);
    const int bKoff = ((lane >> 3) & 1) << 3;

    #pragma unroll 1
    for (int kc = 0; kc < NCH; ++kc) {
        if (kc >= NCH - 2) asm volatile("cp.async.wait_group 0;" ::: "memory");
        else               asm volatile("cp.async.wait_group 1;" ::: "memory");
        __syncthreads();   // single barrier per chunk: orders stage reuse AND data ready

        uint32_t ab = asBase + (uint32_t)(kc % 3) * GEMM_STAGE;
        uint32_t bb = bsBase + (uint32_t)(kc % 3) * GEMM_STAGE;

        // phase 1: all fragment loads
        uint32_t a_r[2][4][4];
        uint32_t b_r[2][4][2];
        #pragma unroll
        for (int ks = 0; ks < 2; ks++) {
            #pragma unroll
            for (int mi = 0; mi < 4; mi++)
                ldm_x4(a_r[ks][mi], ab + (uint32_t)(aRowL + mi * 16) * (PADK * 2)
                                      + (uint32_t)(ks * 16 + aKoff) * 2);
            #pragma unroll
            for (int np = 0; np < 2; np++) {
                uint32_t r[4];
                ldm_x4(r, bb + (uint32_t)(bRowL + np * 16) * (PADK * 2)
                            + (uint32_t)(ks * 16 + bKoff) * 2);
                b_r[ks][np*2][0] = r[0]; b_r[ks][np*2][1] = r[1];
                b_r[ks][np*2+1][0] = r[2]; b_r[ks][np*2+1][1] = r[3];
            }
        }
        // prefetch into stage (kc+2)%3 = (kc-1)%3, consumed at kc-1; safe past the sync
        if (kc + 2 < NCH) load_chunk(kc + 2);

        // phase 2: all mma
        #pragma unroll
        for (int ks = 0; ks < 2; ks++)
            #pragma unroll
            for (int mi = 0; mi < 4; mi++)
                #pragma unroll
                for (int ni = 0; ni < 4; ni++)
                    mma_fp(acc[mi][ni], a_r[ks][mi], b_r[ks][ni]);
    }

    const int mBase = mTile * 128 + warp_m * 64;
    const int nBase = nTile * 128 + warp_n * 32;
    const int rq = lane >> 2, cq = (lane & 3) * 2;

    if (MODE == 0) {
        const int part = (nTile * 128) >> 10;   // 0=Q, 1=K, 2=V
        #pragma unroll
        for (int mi = 0; mi < 4; mi++)
            #pragma unroll
            for (int ni = 0; ni < 4; ni++) {
                int col = nBase + ni * 8 + cq;
                float2 bv = *(const float2*)&bias[col];
                int h = (col & 1023) >> 6, d = col & 63;
                #pragma unroll
                for (int h2 = 0; h2 < 2; h2++) {
                    int row = mBase + mi * 16 + rq + h2 * 8;
                    int b = row >> 11, n = row & 2047;
                    size_t idx = (((size_t)(b * NH + h)) * SEQ + n) * HD + d;
                    float v0 = acc[mi][ni][h2*2]   + bv.x;
                    float v1 = acc[mi][ni][h2*2+1] + bv.y;
                    if (part == 0)      store_h2(g_Qh, idx, v0 * QSCALE, v1 * QSCALE);
                    else if (part == 1) store_h2(g_Kh, idx, v0, v1);
                    else                store_h2(g_Vh, idx, v0, v1);
                }
            }
    } else {
        #pragma unroll
        for (int mi = 0; mi < 4; mi++)
            #pragma unroll
            for (int ni = 0; ni < 4; ni++) {
                int col = nBase + ni * 8 + cq;
                float2 bv = *(const float2*)&bias[col];
                #pragma unroll
                for (int h2 = 0; h2 < 2; h2++) {
                    int row = mBase + mi * 16 + rq + h2 * 8;
                    float2 v = make_float2(acc[mi][ni][h2*2] + bv.x,
                                           acc[mi][ni][h2*2+1] + bv.y);
                    *(float2*)&out[(size_t)row * CDIM + col] = v;
                }
            }
    }
}

// ---------------- flash attention: fp16 QK, single-term PV, 3-stage single-sync --
__global__ __launch_bounds__(128)
void attn_mma()
{
    extern __shared__ char sm_[];
    const int tid  = threadIdx.x;
    const int lane = tid & 31, wid = tid >> 5;
    const int bh = blockIdx.y, qt = blockIdx.x;
    const int b = bh >> 4, h = bh & 15;
    constexpr int NT = SEQ / 64;

    const uint32_t QS  = smem_u32(sm_);
    const uint32_t KV0 = QS + QSMEM_BYTES;
    const size_t ghead = (size_t)bh * SEQ * HD;

    {   // Q tile: 128 rows x 64 fp16
        const __half* qs = g_Qh + ghead + ((size_t)qt * 128 + tid) * HD;
        uint32_t dst = QS + (uint32_t)tid * QROWB;
        #pragma unroll
        for (int s = 0; s < 8; s++) cp16(dst + s*16, qs + s*8);
        cp_commit();
    }

    auto load_kv = [&](int kt) {
        int r = tid >> 1, half = tid & 1;
        const size_t grow = ghead + ((size_t)kt * 64 + r) * HD + half * 32;
        const uint32_t base = KV0 + (uint32_t)(kt % 3) * KVBUF;
        uint32_t kdst = base + (uint32_t)r * KROWB + (uint32_t)half * 64;
        const __half* ks = g_Kh + grow;
        #pragma unroll
        for (int i = 0; i < 4; i++) cp16(kdst + i*16, ks + i*8);
        uint32_t vdst = base + KTILE + (uint32_t)r * VROWB + (uint32_t)half * 64;
        const __half* vs = g_Vh + grow;
        #pragma unroll
        for (int i = 0; i < 4; i++) cp16(vdst + i*16, vs + i*8);
        cp_commit();
    };
    load_kv(0);
    load_kv(1);

    asm volatile("cp.async.wait_group 2;" ::: "memory");   // Q ready
    __syncthreads();

    const int wrow = wid * 32;
    uint32_t qf[2][4][4];
    #pragma unroll
    for (int mi = 0; mi < 2; mi++) {
        uint32_t rowa = QS + (uint32_t)(wrow + mi*16 + (lane & 15)) * QROWB
                      + (uint32_t)((lane >> 4) << 4);
        #pragma unroll
        for (int k = 0; k < 4; k++) ldm_x4(qf[mi][k], rowa + k*32);
    }

    float oc[2][8][4];
    #pragma unroll
    for (int mi = 0; mi < 2; mi++)
        #pragma unroll
        for (int n = 0; n < 8; n++)
            #pragma unroll
            for (int q = 0; q < 4; q++) oc[mi][n][q] = 0.0f;
    ull lacc[2][2];
    lacc[0][0] = lacc[0][1] = lacc[1][0] = lacc[1][1] = pack2(0.0f, 0.0f);

    #pragma unroll 1
    for (int kt = 0; kt < NT; ++kt) {
        if (kt >= NT - 2) asm volatile("cp.async.wait_group 0;" ::: "memory");
        else              asm volatile("cp.async.wait_group 1;" ::: "memory");
        __syncthreads();   // single barrier per tile

        const uint32_t Kb = KV0 + (uint32_t)(kt % 3) * KVBUF;
        const uint32_t Vb = Kb + KTILE;

        float sc[2][8][4];
        #pragma unroll
        for (int mi = 0; mi < 2; mi++)
            #pragma unroll
            for (int n = 0; n < 8; n++)
                #pragma unroll
                for (int q = 0; q < 4; q++) sc[mi][n][q] = 0.0f;

        #pragma unroll
        for (int kk = 0; kk < 4; kk++) {
            uint32_t br[4][4];
            #pragma unroll
            for (int np = 0; np < 4; np++)
                ldm_x4(br[np], Kb + (uint32_t)(np*16 + ((lane >> 4) << 3) + (lane & 7)) * KROWB
                                 + (uint32_t)(kk*16 + (((lane >> 3) & 1) << 3)) * 2);
            #pragma unroll
            for (int mi = 0; mi < 2; mi++) {
                #pragma unroll
                for (int np = 0; np < 4; np++) {
                    mma_fp(sc[mi][np*2],   qf[mi][kk], &br[np][0]);
                    mma_fp(sc[mi][np*2+1], qf[mi][kk], &br[np][2]);
                }
            }
        }

        // prefetch into stage (kt+2)%3 = (kt-1)%3, consumed at kt-1; safe past the sync
        if (kt + 2 < NT) load_kv(kt + 2);

        // exp2 -> P (single fp16) -> PV (single term)
        #pragma unroll
        for (int kk = 0; kk < 4; kk++) {
            uint32_t aP[2][4];
            #pragma unroll
            for (int mi = 0; mi < 2; mi++) {
                #pragma unroll
                for (int half = 0; half < 2; half++) {
                    int n = 2*kk + half;
                    ull p01 = exp2pair(pack2(sc[mi][n][0], sc[mi][n][1]));
                    ull p23 = exp2pair(pack2(sc[mi][n][2], sc[mi][n][3]));
                    lacc[mi][0] = add2(lacc[mi][0], p01);
                    lacc[mi][1] = add2(lacc[mi][1], p23);
                    aP[mi][half*2]   = h2pack(unpack2(p01));
                    aP[mi][half*2+1] = h2pack(unpack2(p23));
                }
            }
            const uint32_t krow = (uint32_t)(kk*16 + ((lane >> 3) & 1) * 8 + (lane & 7));
            #pragma unroll
            for (int nb = 0; nb < 4; nb++) {
                uint32_t bv[4];
                ldm_x4_t(bv, Vb + krow * VROWB + (uint32_t)(nb*16 + ((lane >> 4) << 3)) * 2);
                #pragma unroll
                for (int mi = 0; mi < 2; mi++) {
                    mma_fp(oc[mi][nb*2],   aP[mi], &bv[0]);
                    mma_fp(oc[mi][nb*2+1], aP[mi], &bv[2]);
                }
            }
        }
    }

    // normalize + single-fp16 write to [B,N,H*D]
    #pragma unroll
    for (int mi = 0; mi < 2; mi++) {
        float2 L0 = unpack2(lacc[mi][0]);
        float l0 = L0.x + L0.y;
        l0 += __shfl_xor_sync(0xFFFFFFFFu, l0, 1);
        l0 += __shfl_xor_sync(0xFFFFFFFFu, l0, 2);
        float2 L1 = unpack2(lacc[mi][1]);
        float l1 = L1.x + L1.y;
        l1 += __shfl_xor_sync(0xFFFFFFFFu, l1, 1);
        l1 += __shfl_xor_sync(0xFFFFFFFFu, l1, 2);
        float inv0 = 1.0f / l0, inv1 = 1.0f / l1;
        int r0 = qt * 128 + wrow + mi*16 + (lane >> 2);
        #pragma unroll
        for (int ni = 0; ni < 8; ni++) {
            int d = ni*8 + (lane & 3)*2;
            size_t i0 = ((size_t)(b * SEQ + r0)) * CDIM + h * HD + d;
            size_t i1 = ((size_t)(b * SEQ + r0 + 8)) * CDIM + h * HD + d;
            store_h2(g_Oh, i0, oc[mi][ni][0]*inv0, oc[mi][ni][1]*inv0);
            store_h2(g_Oh, i1, oc[mi][ni][2]*inv1, oc[mi][ni][3]*inv1);
        }
    }
}

// ---------------- launch ----------------
extern "C" void kernel_launch(void* const* d_in, const int* in_sizes, int n_in,
                              void* d_out, int out_size)
{
    const float* x      = (const float*)d_in[0];
    const float* W_qkv  = (const float*)d_in[1];
    const float* b_qkv  = (const float*)d_in[2];
    const float* W_proj = (const float*)d_in[3];
    const float* b_proj = (const float*)d_in[4];
    float* out = (float*)d_out;

    cudaFuncSetAttribute(attn_mma, cudaFuncAttributeMaxDynamicSharedMemorySize, ATTN_SMEM);
    cudaFuncSetAttribute(gemm_fp16<0>, cudaFuncAttributeMaxDynamicSharedMemorySize, GEMM_SMEM);
    cudaFuncSetAttribute(gemm_fp16<1>, cudaFuncAttributeMaxDynamicSharedMemorySize, GEMM_SMEM);

    conv_x<<<(MROWS * KDIM / 4 + 255) / 256, 256>>>(x, MROWS * KDIM / 4);
    {
        dim3 bdim(32, 8);
        dim3 gq(NQKV / 32, KDIM / 32);
        conv_w<0><<<gq, bdim>>>(W_qkv, NQKV);
        dim3 gp(CDIM / 32, KDIM / 32);
        conv_w<1><<<gp, bdim>>>(W_proj, CDIM);
    }
    {
        dim3 g(NQKV / 128, MROWS / 128);
        gemm_fp16<0><<<g, 256, GEMM_SMEM>>>(b_qkv, nullptr);
    }
    {
        dim3 ga(SEQ / 128, BB * NH);
        attn_mma<<<ga, 128, ATTN_SMEM>>>();
    }
    {
        dim3 g(CDIM / 128, MROWS / 128);
        gemm_fp16<1><<<g, 256, GEMM_SMEM>>>(b_proj, out);
    }
}

// round 16
// speedup vs baseline: 1.2676x; 1.0029x over previous
#include <cuda_runtime.h>
#include <cuda_fp16.h>
#include <cstdint>
#include <math.h>

#define BB   4
#define SEQ  2048
#define CDIM 1024
#define NH   16
#define HD   64
#define MROWS (BB*SEQ)
#define KDIM 1024
#define NQKV 3072
#define BK   32
#define PADK 40
#define NCHUNK_QKV 32          // K' = 1024/32 (single fp16 term)
#define NCHUNK_PROJ 32

#define GEMM_STAGE (128*PADK*2)            // 10240 B per operand per stage
#define GEMM_SMEM  (6*GEMM_STAGE)          // 61440 B: A x3 stages, B x3 stages

// attention smem geometry (3 KV stages)
#define QROWB 144
#define QSMEM_BYTES (128*QROWB)            // 18432
#define KROWB 144
#define KTILE (64*KROWB)                   // 9216
#define VROWB 144
#define VTILE (64*VROWB)                   // 9216
#define KVBUF (KTILE+VTILE)                // 18432
#define ATTN_SMEM (QSMEM_BYTES + 3*KVBUF)  // 73728

#define QSCALE 0.1803368801111179f         // 0.125 * log2(e)

// ---------------- scratch ----------------
__device__ __half g_Qh[BB*NH*SEQ*HD];      // [B,H,N,D] fp16, pre-scaled
__device__ __half g_Kh[BB*NH*SEQ*HD];
__device__ __half g_Vh[BB*NH*SEQ*HD];
__device__ __half g_Ah[MROWS*KDIM];        // x single fp16
__device__ __half g_Wq[NQKV*KDIM];         // W_qkv^T single fp16 [N,K]
__device__ __half g_Oh[MROWS*CDIM];        // attention out single fp16 [B,N,H*D]
__device__ __half g_Wp[CDIM*KDIM];         // W_proj^T single fp16 [N,K]

// ---------------- helpers ----------------
typedef unsigned long long ull;

__device__ __forceinline__ uint32_t smem_u32(const void* p) {
    return (uint32_t)__cvta_generic_to_shared(p);
}
__device__ __forceinline__ ull ffma2(ull a, ull b, ull c) {
    ull d; asm("fma.rn.f32x2 %0, %1, %2, %3;" : "=l"(d) : "l"(a), "l"(b), "l"(c)); return d;
}
__device__ __forceinline__ ull add2(ull a, ull b) {
    ull d; asm("add.rn.f32x2 %0, %1, %2;" : "=l"(d) : "l"(a), "l"(b)); return d;
}
__device__ __forceinline__ ull pack2(float lo, float hi) {
    ull r; asm("mov.b64 %0, {%1, %2};" : "=l"(r) : "f"(lo), "f"(hi)); return r;
}
__device__ __forceinline__ float2 unpack2(ull v) {
    float lo, hi; asm("mov.b64 {%0, %1}, %2;" : "=f"(lo), "=f"(hi) : "l"(v));
    return make_float2(lo, hi);
}
__device__ __forceinline__ void cp16(uint32_t dst, const void* src) {
    asm volatile("cp.async.cg.shared.global [%0], [%1], 16;" :: "r"(dst), "l"(src));
}
__device__ __forceinline__ void cp_commit() { asm volatile("cp.async.commit_group;"); }
__device__ __forceinline__ void ldm_x4(uint32_t* r, uint32_t addr) {
    asm volatile("ldmatrix.sync.aligned.m8n8.x4.shared.b16 {%0,%1,%2,%3}, [%4];"
                 : "=r"(r[0]), "=r"(r[1]), "=r"(r[2]), "=r"(r[3]) : "r"(addr));
}
__device__ __forceinline__ void ldm_x4_t(uint32_t* r, uint32_t addr) {
    asm volatile("ldmatrix.sync.aligned.m8n8.x4.trans.shared.b16 {%0,%1,%2,%3}, [%4];"
                 : "=r"(r[0]), "=r"(r[1]), "=r"(r[2]), "=r"(r[3]) : "r"(addr));
}
__device__ __forceinline__ void mma_fp(float* c, const uint32_t* a, const uint32_t* b) {
    asm volatile(
        "mma.sync.aligned.m16n8k16.row.col.f32.f16.f16.f32 "
        "{%0,%1,%2,%3}, {%4,%5,%6,%7}, {%8,%9}, {%0,%1,%2,%3};"
        : "+f"(c[0]), "+f"(c[1]), "+f"(c[2]), "+f"(c[3])
        : "r"(a[0]), "r"(a[1]), "r"(a[2]), "r"(a[3]), "r"(b[0]), "r"(b[1]));
}
__device__ __forceinline__ void store_h2(__half* A, size_t idx, float v0, float v1) {
    uint32_t r; asm("cvt.rn.f16x2.f32 %0, %1, %2;" : "=r"(r) : "f"(v1), "f"(v0));
    *(uint32_t*)&A[idx] = r;
}
__device__ __forceinline__ uint32_t h2pack(float2 v) {
    uint32_t r; asm("cvt.rn.f16x2.f32 %0, %1, %2;" : "=r"(r) : "f"(v.y), "f"(v.x));
    return r;
}

#define MAGICF 12582912.0f
// degree-4 2^f poly on f in [-0.5, 0.5]; max rel err ~1e-6
__device__ __forceinline__ ull exp2pair(ull t) {
    const ull MAGIC2  = pack2(MAGICF, MAGICF);
    const ull NMAGIC2 = pack2(-MAGICF, -MAGICF);
    const ull NONE2   = pack2(-1.0f, -1.0f);
    const ull ONE2    = pack2(1.0f, 1.0f);
    const ull C1 = pack2(0.6931471971938464f, 0.6931471971938464f);
    const ull C2 = pack2(0.2402264689063408f, 0.2402264689063408f);
    const ull C3 = pack2(0.0555042108516768f, 0.0555042108516768f);
    const ull C4 = pack2(0.0096181289721693f, 0.0096181289721693f);
    ull m = add2(t, MAGIC2);
    ull kf = add2(m, NMAGIC2);
    ull f = ffma2(kf, NONE2, t);
    ull p = ffma2(C4, f, C3);
    p = ffma2(p, f, C2); p = ffma2(p, f, C1); p = ffma2(p, f, ONE2);
    float2 mf = unpack2(m); float2 pf = unpack2(p);
    uint32_t r0 = __float_as_uint(pf.x) + (__float_as_uint(mf.x) << 23);
    uint32_t r1 = __float_as_uint(pf.y) + (__float_as_uint(mf.y) << 23);
    return pack2(__uint_as_float(r0), __uint_as_float(r1));
}

// ---------------- conversion kernels ----------------
__global__ void conv_x(const float* __restrict__ src, int n4)
{
    int i = blockIdx.x * blockDim.x + threadIdx.x;
    if (i >= n4) return;
    float4 v = ((const float4*)src)[i];
    union { uint2 u; __half h[4]; } ph;
    ph.h[0] = __float2half_rn(v.x);
    ph.h[1] = __float2half_rn(v.y);
    ph.h[2] = __float2half_rn(v.z);
    ph.h[3] = __float2half_rn(v.w);
    ((uint2*)g_Ah)[i] = ph.u;
}

template <int SEL>
__global__ void conv_w(const float* __restrict__ W, int Nd)
{
    __shared__ float t[32][33];
    __half* dst = SEL ? g_Wp : g_Wq;
    int n0 = blockIdx.x * 32, k0 = blockIdx.y * 32;
    #pragma unroll
    for (int i = 0; i < 4; i++) {
        int k = k0 + threadIdx.y + i * 8;
        t[threadIdx.y + i * 8][threadIdx.x] = W[(size_t)k * Nd + n0 + threadIdx.x];
    }
    __syncthreads();
    #pragma unroll
    for (int i = 0; i < 4; i++) {
        int n = n0 + threadIdx.y + i * 8;
        int k = k0 + threadIdx.x;
        dst[(size_t)n * KDIM + k] = __float2half_rn(t[threadIdx.x][threadIdx.y + i * 8]);
    }
}

// ---------------- fp16 GEMM: 128x128 tile, warp 64x32, 3-stage single-sync ----
template <int MODE>
__global__ __launch_bounds__(256, 2)
void gemm_fp16(const float* __restrict__ bias, float* __restrict__ out)
{
    constexpr int NCH = (MODE == 0) ? NCHUNK_QKV : NCHUNK_PROJ;
    extern __shared__ char gsm[];

    const int tid = threadIdx.x;
    const int lane = tid & 31, wid = tid >> 5;
    const int warp_m = wid >> 2, warp_n = wid & 3;
    const int mTile = blockIdx.y, nTile = blockIdx.x;
    const int aRow0 = mTile * 128, bRow0 = nTile * 128;
    const int lrow = tid >> 2, lseg = tid & 3;

    const uint32_t asBase = smem_u32(gsm);
    const uint32_t bsBase = asBase + 3 * GEMM_STAGE;

    auto load_chunk = [&](int kc) {
        int k0 = kc * BK;
        const __half* Ap = (MODE == 0) ? g_Ah : g_Oh;
        const __half* Bp = (MODE == 0) ? g_Wq : g_Wp;
        uint32_t so = (uint32_t)(kc % 3) * GEMM_STAGE;
        #pragma unroll
        for (int i = 0; i < 2; i++) {
            int row = lrow + 64 * i;
            uint32_t doff = so + (uint32_t)row * (PADK * 2) + (uint32_t)lseg * 16;
            cp16(asBase + doff, Ap + (size_t)(aRow0 + row) * KDIM + k0 + lseg * 8);
            cp16(bsBase + doff, Bp + (size_t)(bRow0 + row) * KDIM + k0 + lseg * 8);
        }
        cp_commit();
    };

    float acc[4][4][4];
    #pragma unroll
    for (int mi = 0; mi < 4; mi++)
        #pragma unroll
        for (int ni = 0; ni < 4; ni++)
            #pragma unroll
            for (int q = 0; q < 4; q++) acc[mi][ni][q] = 0.0f;

    load_chunk(0);
    load_chunk(1);

    const int aRowL = warp_m * 64 + (lane & 15);
    const int aKoff = (lane >> 4) << 3;
    const int bRowL = warp_n * 32 + ((lane >> 4) << 3) + (lane & 7);
    const int bKoff = ((lane >> 3) & 1) << 3;

    #pragma unroll 1
    for (int kc = 0; kc < NCH; ++kc) {
        if (kc >= NCH - 2) asm volatile("cp.async.wait_group 0;" ::: "memory");
        else               asm volatile("cp.async.wait_group 1;" ::: "memory");
        __syncthreads();   // single barrier per chunk: orders stage reuse AND data ready

        uint32_t ab = asBase + (uint32_t)(kc % 3) * GEMM_STAGE;
        uint32_t bb = bsBase + (uint32_t)(kc % 3) * GEMM_STAGE;

        // phase 1: all fragment loads
        uint32_t a_r[2][4][4];
        uint32_t b_r[2][4][2];
        #pragma unroll
        for (int ks = 0; ks < 2; ks++) {
            #pragma unroll
            for (int mi = 0; mi < 4; mi++)
                ldm_x4(a_r[ks][mi], ab + (uint32_t)(aRowL + mi * 16) * (PADK * 2)
                                      + (uint32_t)(ks * 16 + aKoff) * 2);
            #pragma unroll
            for (int np = 0; np < 2; np++) {
                uint32_t r[4];
                ldm_x4(r, bb + (uint32_t)(bRowL + np * 16) * (PADK * 2)
                            + (uint32_t)(ks * 16 + bKoff) * 2);
                b_r[ks][np*2][0] = r[0]; b_r[ks][np*2][1] = r[1];
                b_r[ks][np*2+1][0] = r[2]; b_r[ks][np*2+1][1] = r[3];
            }
        }
        // prefetch into stage (kc+2)%3 = (kc-1)%3, consumed at kc-1; safe past the sync
        if (kc + 2 < NCH) load_chunk(kc + 2);

        // phase 2: all mma
        #pragma unroll
        for (int ks = 0; ks < 2; ks++)
            #pragma unroll
            for (int mi = 0; mi < 4; mi++)
                #pragma unroll
                for (int ni = 0; ni < 4; ni++)
                    mma_fp(acc[mi][ni], a_r[ks][mi], b_r[ks][ni]);
    }

    const int mBase = mTile * 128 + warp_m * 64;
    const int nBase = nTile * 128 + warp_n * 32;
    const int rq = lane >> 2, cq = (lane & 3) * 2;

    if (MODE == 0) {
        const int part = (nTile * 128) >> 10;   // 0=Q, 1=K, 2=V
        #pragma unroll
        for (int mi = 0; mi < 4; mi++)
            #pragma unroll
            for (int ni = 0; ni < 4; ni++) {
                int col = nBase + ni * 8 + cq;
                float2 bv = *(const float2*)&bias[col];
                int h = (col & 1023) >> 6, d = col & 63;
                #pragma unroll
                for (int h2 = 0; h2 < 2; h2++) {
                    int row = mBase + mi * 16 + rq + h2 * 8;
                    int b = row >> 11, n = row & 2047;
                    size_t idx = (((size_t)(b * NH + h)) * SEQ + n) * HD + d;
                    float v0 = acc[mi][ni][h2*2]   + bv.x;
                    float v1 = acc[mi][ni][h2*2+1] + bv.y;
                    if (part == 0)      store_h2(g_Qh, idx, v0 * QSCALE, v1 * QSCALE);
                    else if (part == 1) store_h2(g_Kh, idx, v0, v1);
                    else                store_h2(g_Vh, idx, v0, v1);
                }
            }
    } else {
        #pragma unroll
        for (int mi = 0; mi < 4; mi++)
            #pragma unroll
            for (int ni = 0; ni < 4; ni++) {
                int col = nBase + ni * 8 + cq;
                float2 bv = *(const float2*)&bias[col];
                #pragma unroll
                for (int h2 = 0; h2 < 2; h2++) {
                    int row = mBase + mi * 16 + rq + h2 * 8;
                    float2 v = make_float2(acc[mi][ni][h2*2] + bv.x,
                                           acc[mi][ni][h2*2+1] + bv.y);
                    *(float2*)&out[(size_t)row * CDIM + col] = v;
                }
            }
    }
}

// ---------------- flash attention: fp16 QK, single-term PV, 3-stage single-sync --
__global__ __launch_bounds__(128)
void attn_mma()
{
    extern __shared__ char sm_[];
    const int tid  = threadIdx.x;
    const int lane = tid & 31, wid = tid >> 5;
    const int bh = blockIdx.y, qt = blockIdx.x;
    const int b = bh >> 4, h = bh & 15;
    constexpr int NT = SEQ / 64;

    const uint32_t QS  = smem_u32(sm_);
    const uint32_t KV0 = QS + QSMEM_BYTES;
    const size_t ghead = (size_t)bh * SEQ * HD;

    {   // Q tile: 128 rows x 64 fp16
        const __half* qs = g_Qh + ghead + ((size_t)qt * 128 + tid) * HD;
        uint32_t dst = QS + (uint32_t)tid * QROWB;
        #pragma unroll
        for (int s = 0; s < 8; s++) cp16(dst + s*16, qs + s*8);
        cp_commit();
    }

    auto load_kv = [&](int kt) {
        int r = tid >> 1, half = tid & 1;
        const size_t grow = ghead + ((size_t)kt * 64 + r) * HD + half * 32;
        const uint32_t base = KV0 + (uint32_t)(kt % 3) * KVBUF;
        uint32_t kdst = base + (uint32_t)r * KROWB + (uint32_t)half * 64;
        const __half* ks = g_Kh + grow;
        #pragma unroll
        for (int i = 0; i < 4; i++) cp16(kdst + i*16, ks + i*8);
        uint32_t vdst = base + KTILE + (uint32_t)r * VROWB + (uint32_t)half * 64;
        const __half* vs = g_Vh + grow;
        #pragma unroll
        for (int i = 0; i < 4; i++) cp16(vdst + i*16, vs + i*8);
        cp_commit();
    };
    load_kv(0);
    load_kv(1);

    asm volatile("cp.async.wait_group 2;" ::: "memory");   // Q ready
    __syncthreads();

    const int wrow = wid * 32;
    uint32_t qf[2][4][4];
    #pragma unroll
    for (int mi = 0; mi < 2; mi++) {
        uint32_t rowa = QS + (uint32_t)(wrow + mi*16 + (lane & 15)) * QROWB
                      + (uint32_t)((lane >> 4) << 4);
        #pragma unroll
        for (int k = 0; k < 4; k++) ldm_x4(qf[mi][k], rowa + k*32);
    }

    float oc[2][8][4];
    #pragma unroll
    for (int mi = 0; mi < 2; mi++)
        #pragma unroll
        for (int n = 0; n < 8; n++)
            #pragma unroll
            for (int q = 0; q < 4; q++) oc[mi][n][q] = 0.0f;
    ull lacc[2][2];
    lacc[0][0] = lacc[0][1] = lacc[1][0] = lacc[1][1] = pack2(0.0f, 0.0f);

    #pragma unroll 1
    for (int kt = 0; kt < NT; ++kt) {
        if (kt >= NT - 2) asm volatile("cp.async.wait_group 0;" ::: "memory");
        else              asm volatile("cp.async.wait_group 1;" ::: "memory");
        __syncthreads();   // single barrier per tile

        const uint32_t Kb = KV0 + (uint32_t)(kt % 3) * KVBUF;
        const uint32_t Vb = Kb + KTILE;

        float sc[2][8][4];
        #pragma unroll
        for (int mi = 0; mi < 2; mi++)
            #pragma unroll
            for (int n = 0; n < 8; n++)
                #pragma unroll
                for (int q = 0; q < 4; q++) sc[mi][n][q] = 0.0f;

        #pragma unroll
        for (int kk = 0; kk < 4; kk++) {
            uint32_t br[4][4];
            #pragma unroll
            for (int np = 0; np < 4; np++)
                ldm_x4(br[np], Kb + (uint32_t)(np*16 + ((lane >> 4) << 3) + (lane & 7)) * KROWB
                                 + (uint32_t)(kk*16 + (((lane >> 3) & 1) << 3)) * 2);
            #pragma unroll
            for (int mi = 0; mi < 2; mi++) {
                #pragma unroll
                for (int np = 0; np < 4; np++) {
                    mma_fp(sc[mi][np*2],   qf[mi][kk], &br[np][0]);
                    mma_fp(sc[mi][np*2+1], qf[mi][kk], &br[np][2]);
                }
            }
        }

        // prefetch into stage (kt+2)%3 = (kt-1)%3, consumed at kt-1; safe past the sync
        if (kt + 2 < NT) load_kv(kt + 2);

        // exp2 -> P (single fp16) -> PV (single term)
        #pragma unroll
        for (int kk = 0; kk < 4; kk++) {
            uint32_t aP[2][4];
            #pragma unroll
            for (int mi = 0; mi < 2; mi++) {
                #pragma unroll
                for (int half = 0; half < 2; half++) {
                    int n = 2*kk + half;
                    ull p01 = exp2pair(pack2(sc[mi][n][0], sc[mi][n][1]));
                    ull p23 = exp2pair(pack2(sc[mi][n][2], sc[mi][n][3]));
                    lacc[mi][0] = add2(lacc[mi][0], p01);
                    lacc[mi][1] = add2(lacc[mi][1], p23);
                    aP[mi][half*2]   = h2pack(unpack2(p01));
                    aP[mi][half*2+1] = h2pack(unpack2(p23));
                }
            }
            const uint32_t krow = (uint32_t)(kk*16 + ((lane >> 3) & 1) * 8 + (lane & 7));
            #pragma unroll
            for (int nb = 0; nb < 4; nb++) {
                uint32_t bv[4];
                ldm_x4_t(bv, Vb + krow * VROWB + (uint32_t)(nb*16 + ((lane >> 4) << 3)) * 2);
                #pragma unroll
                for (int mi = 0; mi < 2; mi++) {
                    mma_fp(oc[mi][nb*2],   aP[mi], &bv[0]);
                    mma_fp(oc[mi][nb*2+1], aP[mi], &bv[2]);
                }
            }
        }
    }

    // normalize + single-fp16 write to [B,N,H*D]
    #pragma unroll
    for (int mi = 0; mi < 2; mi++) {
        float2 L0 = unpack2(lacc[mi][0]);
        float l0 = L0.x + L0.y;
        l0 += __shfl_xor_sync(0xFFFFFFFFu, l0, 1);
        l0 += __shfl_xor_sync(0xFFFFFFFFu, l0, 2);
        float2 L1 = unpack2(lacc[mi][1]);
        float l1 = L1.x + L1.y;
        l1 += __shfl_xor_sync(0xFFFFFFFFu, l1, 1);
        l1 += __shfl_xor_sync(0xFFFFFFFFu, l1, 2);
        float inv0 = 1.0f / l0, inv1 = 1.0f / l1;
        int r0 = qt * 128 + wrow + mi*16 + (lane >> 2);
        #pragma unroll
        for (int ni = 0; ni < 8; ni++) {
            int d = ni*8 + (lane & 3)*2;
            size_t i0 = ((size_t)(b * SEQ + r0)) * CDIM + h * HD + d;
            size_t i1 = ((size_t)(b * SEQ + r0 + 8)) * CDIM + h * HD + d;
            store_h2(g_Oh, i0, oc[mi][ni][0]*inv0, oc[mi][ni][1]*inv0);
            store_h2(g_Oh, i1, oc[mi][ni][2]*inv1, oc[mi][ni][3]*inv1);
        }
    }
}

// ---------------- launch ----------------
extern "C" void kernel_launch(void* const* d_in, const int* in_sizes, int n_in,
                              void* d_out, int out_size)
{
    const float* x      = (const float*)d_in[0];
    const float* W_qkv  = (const float*)d_in[1];
    const float* b_qkv  = (const float*)d_in[2];
    const float* W_proj = (const float*)d_in[3];
    const float* b_proj = (const float*)d_in[4];
    float* out = (float*)d_out;

    cudaFuncSetAttribute(attn_mma, cudaFuncAttributeMaxDynamicSharedMemorySize, ATTN_SMEM);
    cudaFuncSetAttribute(gemm_fp16<0>, cudaFuncAttributeMaxDynamicSharedMemorySize, GEMM_SMEM);
    cudaFuncSetAttribute(gemm_fp16<1>, cudaFuncAttributeMaxDynamicSharedMemorySize, GEMM_SMEM);

    conv_x<<<(MROWS * KDIM / 4 + 255) / 256, 256>>>(x, MROWS * KDIM / 4);
    {
        dim3 bdim(32, 8);
        dim3 gq(NQKV / 32, KDIM / 32);
        conv_w<0><<<gq, bdim>>>(W_qkv, NQKV);
        dim3 gp(CDIM / 32, KDIM / 32);
        conv_w<1><<<gp, bdim>>>(W_proj, CDIM);
    }
    {
        dim3 g(NQKV / 128, MROWS / 128);
        gemm_fp16<0><<<g, 256, GEMM_SMEM>>>(b_qkv, nullptr);
    }
    {
        dim3 ga(SEQ / 128, BB * NH);
        attn_mma<<<ga, 128, ATTN_SMEM>>>();
    }
    {
        dim3 g(CDIM / 128, MROWS / 128);
        gemm_fp16<1><<<g, 256, GEMM_SMEM>>>(b_proj, out);
    }
}

// round 17
// speedup vs baseline: 1.2677x; 1.0001x over previous
#include <cuda_runtime.h>
#include <cuda_fp16.h>
#include <cstdint>
#include <math.h>

#define BB   4
#define SEQ  2048
#define CDIM 1024
#define NH   16
#define HD   64
#define MROWS (BB*SEQ)
#define KDIM 1024
#define NQKV 3072
#define BK   32
#define PADK 40
#define NCHUNK_QKV 32          // K' = 1024/32 (single fp16 term)
#define NCHUNK_PROJ 32

#define GEMM_STAGE (128*PADK*2)            // 10240 B per operand per stage
#define GEMM_SMEM  (6*GEMM_STAGE)          // 61440 B: A x3 stages, B x3 stages

// attention smem geometry (3 KV stages)
#define QROWB 144
#define QSMEM_BYTES (128*QROWB)            // 18432
#define KROWB 144
#define KTILE (64*KROWB)                   // 9216
#define VROWB 144
#define VTILE (64*VROWB)                   // 9216
#define KVBUF (KTILE+VTILE)                // 18432
#define ATTN_SMEM (QSMEM_BYTES + 3*KVBUF)  // 73728

#define QSCALE 0.1803368801111179f         // 0.125 * log2(e)

// ---------------- scratch ----------------
__device__ __half g_Qh[BB*NH*SEQ*HD];      // [B,H,N,D] fp16, pre-scaled
__device__ __half g_Kh[BB*NH*SEQ*HD];
__device__ __half g_Vh[BB*NH*SEQ*HD];
__device__ __half g_Ah[MROWS*KDIM];        // x single fp16
__device__ __half g_Wq[NQKV*KDIM];         // W_qkv^T single fp16 [N,K]
__device__ __half g_Oh[MROWS*CDIM];        // attention out single fp16 [B,N,H*D]
__device__ __half g_Wp[CDIM*KDIM];         // W_proj^T single fp16 [N,K]

// ---------------- helpers ----------------
typedef unsigned long long ull;

__device__ __forceinline__ uint32_t smem_u32(const void* p) {
    return (uint32_t)__cvta_generic_to_shared(p);
}
__device__ __forceinline__ ull ffma2(ull a, ull b, ull c) {
    ull d; asm("fma.rn.f32x2 %0, %1, %2, %3;" : "=l"(d) : "l"(a), "l"(b), "l"(c)); return d;
}
__device__ __forceinline__ ull add2(ull a, ull b) {
    ull d; asm("add.rn.f32x2 %0, %1, %2;" : "=l"(d) : "l"(a), "l"(b)); return d;
}
__device__ __forceinline__ ull pack2(float lo, float hi) {
    ull r; asm("mov.b64 %0, {%1, %2};" : "=l"(r) : "f"(lo), "f"(hi)); return r;
}
__device__ __forceinline__ float2 unpack2(ull v) {
    float lo, hi; asm("mov.b64 {%0, %1}, %2;" : "=f"(lo), "=f"(hi) : "l"(v));
    return make_float2(lo, hi);
}
__device__ __forceinline__ void cp16(uint32_t dst, const void* src) {
    asm volatile("cp.async.cg.shared.global [%0], [%1], 16;" :: "r"(dst), "l"(src));
}
__device__ __forceinline__ void cp_commit() { asm volatile("cp.async.commit_group;"); }
__device__ __forceinline__ void ldm_x4(uint32_t* r, uint32_t addr) {
    asm volatile("ldmatrix.sync.aligned.m8n8.x4.shared.b16 {%0,%1,%2,%3}, [%4];"
                 : "=r"(r[0]), "=r"(r[1]), "=r"(r[2]), "=r"(r[3]) : "r"(addr));
}
__device__ __forceinline__ void ldm_x4_t(uint32_t* r, uint32_t addr) {
    asm volatile("ldmatrix.sync.aligned.m8n8.x4.trans.shared.b16 {%0,%1,%2,%3}, [%4];"
                 : "=r"(r[0]), "=r"(r[1]), "=r"(r[2]), "=r"(r[3]) : "r"(addr));
}
__device__ __forceinline__ void mma_fp(float* c, const uint32_t* a, const uint32_t* b) {
    asm volatile(
        "mma.sync.aligned.m16n8k16.row.col.f32.f16.f16.f32 "
        "{%0,%1,%2,%3}, {%4,%5,%6,%7}, {%8,%9}, {%0,%1,%2,%3};"
        : "+f"(c[0]), "+f"(c[1]), "+f"(c[2]), "+f"(c[3])
        : "r"(a[0]), "r"(a[1]), "r"(a[2]), "r"(a[3]), "r"(b[0]), "r"(b[1]));
}
__device__ __forceinline__ void store_h2(__half* A, size_t idx, float v0, float v1) {
    uint32_t r; asm("cvt.rn.f16x2.f32 %0, %1, %2;" : "=r"(r) : "f"(v1), "f"(v0));
    *(uint32_t*)&A[idx] = r;
}
__device__ __forceinline__ uint32_t h2pack(float2 v) {
    uint32_t r; asm("cvt.rn.f16x2.f32 %0, %1, %2;" : "=r"(r) : "f"(v.y), "f"(v.x));
    return r;
}

#define MAGICF 12582912.0f
// degree-4 2^f poly on f in [-0.5, 0.5]; max rel err ~1e-6
__device__ __forceinline__ ull exp2pair(ull t) {
    const ull MAGIC2  = pack2(MAGICF, MAGICF);
    const ull NMAGIC2 = pack2(-MAGICF, -MAGICF);
    const ull NONE2   = pack2(-1.0f, -1.0f);
    const ull ONE2    = pack2(1.0f, 1.0f);
    const ull C1 = pack2(0.6931471971938464f, 0.6931471971938464f);
    const ull C2 = pack2(0.2402264689063408f, 0.2402264689063408f);
    const ull C3 = pack2(0.0555042108516768f, 0.0555042108516768f);
    const ull C4 = pack2(0.0096181289721693f, 0.0096181289721693f);
    ull m = add2(t, MAGIC2);
    ull kf = add2(m, NMAGIC2);
    ull f = ffma2(kf, NONE2, t);
    ull p = ffma2(C4, f, C3);
    p = ffma2(p, f, C2); p = ffma2(p, f, C1); p = ffma2(p, f, ONE2);
    float2 mf = unpack2(m); float2 pf = unpack2(p);
    uint32_t r0 = __float_as_uint(pf.x) + (__float_as_uint(mf.x) << 23);
    uint32_t r1 = __float_as_uint(pf.y) + (__float_as_uint(mf.y) << 23);
    return pack2(__uint_as_float(r0), __uint_as_float(r1));
}

// ---------------- conversion kernels ----------------
__global__ void conv_x(const float* __restrict__ src, int n4)
{
    int i = blockIdx.x * blockDim.x + threadIdx.x;
    if (i >= n4) return;
    float4 v = ((const float4*)src)[i];
    union { uint2 u; __half h[4]; } ph;
    ph.h[0] = __float2half_rn(v.x);
    ph.h[1] = __float2half_rn(v.y);
    ph.h[2] = __float2half_rn(v.z);
    ph.h[3] = __float2half_rn(v.w);
    ((uint2*)g_Ah)[i] = ph.u;
}

template <int SEL>
__global__ void conv_w(const float* __restrict__ W, int Nd)
{
    __shared__ float t[32][33];
    __half* dst = SEL ? g_Wp : g_Wq;
    int n0 = blockIdx.x * 32, k0 = blockIdx.y * 32;
    #pragma unroll
    for (int i = 0; i < 4; i++) {
        int k = k0 + threadIdx.y + i * 8;
        t[threadIdx.y + i * 8][threadIdx.x] = W[(size_t)k * Nd + n0 + threadIdx.x];
    }
    __syncthreads();
    #pragma unroll
    for (int i = 0; i < 4; i++) {
        int n = n0 + threadIdx.y + i * 8;
        int k = k0 + threadIdx.x;
        dst[(size_t)n * KDIM + k] = __float2half_rn(t[threadIdx.x][threadIdx.y + i * 8]);
    }
}

// ---------------- fp16 GEMM: 128x128 tile, warp 64x32, 3-stage single-sync ----
template <int MODE>
__global__ __launch_bounds__(256, 2)
void gemm_fp16(const float* __restrict__ bias, float* __restrict__ out)
{
    constexpr int NCH = (MODE == 0) ? NCHUNK_QKV : NCHUNK_PROJ;
    extern __shared__ char gsm[];

    const int tid = threadIdx.x;
    const int lane = tid & 31, wid = tid >> 5;
    const int warp_m = wid >> 2, warp_n = wid & 3;
    const int mTile = blockIdx.y, nTile = blockIdx.x;
    const int aRow0 = mTile * 128, bRow0 = nTile * 128;
    const int lrow = tid >> 2, lseg = tid & 3;

    const uint32_t asBase = smem_u32(gsm);
    const uint32_t bsBase = asBase + 3 * GEMM_STAGE;

    auto load_chunk = [&](int kc) {
        int k0 = kc * BK;
        const __half* Ap = (MODE == 0) ? g_Ah : g_Oh;
        const __half* Bp = (MODE == 0) ? g_Wq : g_Wp;
        uint32_t so = (uint32_t)(kc % 3) * GEMM_STAGE;
        #pragma unroll
        for (int i = 0; i < 2; i++) {
            int row = lrow + 64 * i;
            uint32_t doff = so + (uint32_t)row * (PADK * 2) + (uint32_t)lseg * 16;
            cp16(asBase + doff, Ap + (size_t)(aRow0 + row) * KDIM + k0 + lseg * 8);
            cp16(bsBase + doff, Bp + (size_t)(bRow0 + row) * KDIM + k0 + lseg * 8);
        }
        cp_commit();
    };

    float acc[4][4][4];
    #pragma unroll
    for (int mi = 0; mi < 4; mi++)
        #pragma unroll
        for (int ni = 0; ni < 4; ni++)
            #pragma unroll
            for (int q = 0; q < 4; q++) acc[mi][ni][q] = 0.0f;

    load_chunk(0);
    load_chunk(1);

    const int aRowL = warp_m * 64 + (lane & 15);
    const int aKoff = (lane >> 4) << 3;
    const int bRowL = warp_n * 32 + ((lane >> 4) << 3) + (lane & 7);
    const int bKoff = ((lane >> 3) & 1) << 3;

    #pragma unroll 1
    for (int kc = 0; kc < NCH; ++kc) {
        if (kc >= NCH - 2) asm volatile("cp.async.wait_group 0;" ::: "memory");
        else               asm volatile("cp.async.wait_group 1;" ::: "memory");
        __syncthreads();   // single barrier per chunk: orders stage reuse AND data ready

        uint32_t ab = asBase + (uint32_t)(kc % 3) * GEMM_STAGE;
        uint32_t bb = bsBase + (uint32_t)(kc % 3) * GEMM_STAGE;

        // phase 1: all fragment loads
        uint32_t a_r[2][4][4];
        uint32_t b_r[2][4][2];
        #pragma unroll
        for (int ks = 0; ks < 2; ks++) {
            #pragma unroll
            for (int mi = 0; mi < 4; mi++)
                ldm_x4(a_r[ks][mi], ab + (uint32_t)(aRowL + mi * 16) * (PADK * 2)
                                      + (uint32_t)(ks * 16 + aKoff) * 2);
            #pragma unroll
            for (int np = 0; np < 2; np++) {
                uint32_t r[4];
                ldm_x4(r, bb + (uint32_t)(bRowL + np * 16) * (PADK * 2)
                            + (uint32_t)(ks * 16 + bKoff) * 2);
                b_r[ks][np*2][0] = r[0]; b_r[ks][np*2][1] = r[1];
                b_r[ks][np*2+1][0] = r[2]; b_r[ks][np*2+1][1] = r[3];
            }
        }
        // prefetch into stage (kc+2)%3 = (kc-1)%3, consumed at kc-1; safe past the sync
        if (kc + 2 < NCH) load_chunk(kc + 2);

        // phase 2: all mma
        #pragma unroll
        for (int ks = 0; ks < 2; ks++)
            #pragma unroll
            for (int mi = 0; mi < 4; mi++)
                #pragma unroll
                for (int ni = 0; ni < 4; ni++)
                    mma_fp(acc[mi][ni], a_r[ks][mi], b_r[ks][ni]);
    }

    const int mBase = mTile * 128 + warp_m * 64;
    const int nBase = nTile * 128 + warp_n * 32;
    const int rq = lane >> 2, cq = (lane & 3) * 2;

    if (MODE == 0) {
        const int part = (nTile * 128) >> 10;   // 0=Q, 1=K, 2=V
        #pragma unroll
        for (int mi = 0; mi < 4; mi++)
            #pragma unroll
            for (int ni = 0; ni < 4; ni++) {
                int col = nBase + ni * 8 + cq;
                float2 bv = *(const float2*)&bias[col];
                int h = (col & 1023) >> 6, d = col & 63;
                #pragma unroll
                for (int h2 = 0; h2 < 2; h2++) {
                    int row = mBase + mi * 16 + rq + h2 * 8;
                    int b = row >> 11, n = row & 2047;
                    size_t idx = (((size_t)(b * NH + h)) * SEQ + n) * HD + d;
                    float v0 = acc[mi][ni][h2*2]   + bv.x;
                    float v1 = acc[mi][ni][h2*2+1] + bv.y;
                    if (part == 0)      store_h2(g_Qh, idx, v0 * QSCALE, v1 * QSCALE);
                    else if (part == 1) store_h2(g_Kh, idx, v0, v1);
                    else                store_h2(g_Vh, idx, v0, v1);
                }
            }
    } else {
        #pragma unroll
        for (int mi = 0; mi < 4; mi++)
            #pragma unroll
            for (int ni = 0; ni < 4; ni++) {
                int col = nBase + ni * 8 + cq;
                float2 bv = *(const float2*)&bias[col];
                #pragma unroll
                for (int h2 = 0; h2 < 2; h2++) {
                    int row = mBase + mi * 16 + rq + h2 * 8;
                    float2 v = make_float2(acc[mi][ni][h2*2] + bv.x,
                                           acc[mi][ni][h2*2+1] + bv.y);
                    *(float2*)&out[(size_t)row * CDIM + col] = v;
                }
            }
    }
}

// ---------------- flash attention: fp16 QK, single-term PV, 3-stage single-sync --
__global__ __launch_bounds__(128)
void attn_mma()
{
    extern __shared__ char sm_[];
    const int tid  = threadIdx.x;
    const int lane = tid & 31, wid = tid >> 5;
    const int bh = blockIdx.y, qt = blockIdx.x;
    const int b = bh >> 4, h = bh & 15;
    constexpr int NT = SEQ / 64;

    const uint32_t QS  = smem_u32(sm_);
    const uint32_t KV0 = QS + QSMEM_BYTES;
    const size_t ghead = (size_t)bh * SEQ * HD;

    {   // Q tile: 128 rows x 64 fp16
        const __half* qs = g_Qh + ghead + ((size_t)qt * 128 + tid) * HD;
        uint32_t dst = QS + (uint32_t)tid * QROWB;
        #pragma unroll
        for (int s = 0; s < 8; s++) cp16(dst + s*16, qs + s*8);
        cp_commit();
    }

    auto load_kv = [&](int kt) {
        int r = tid >> 1, half = tid & 1;
        const size_t grow = ghead + ((size_t)kt * 64 + r) * HD + half * 32;
        const uint32_t base = KV0 + (uint32_t)(kt % 3) * KVBUF;
        uint32_t kdst = base + (uint32_t)r * KROWB + (uint32_t)half * 64;
        const __half* ks = g_Kh + grow;
        #pragma unroll
        for (int i = 0; i < 4; i++) cp16(kdst + i*16, ks + i*8);
        uint32_t vdst = base + KTILE + (uint32_t)r * VROWB + (uint32_t)half * 64;
        const __half* vs = g_Vh + grow;
        #pragma unroll
        for (int i = 0; i < 4; i++) cp16(vdst + i*16, vs + i*8);
        cp_commit();
    };
    load_kv(0);
    load_kv(1);

    asm volatile("cp.async.wait_group 2;" ::: "memory");   // Q ready
    __syncthreads();

    const int wrow = wid * 32;
    uint32_t qf[2][4][4];
    #pragma unroll
    for (int mi = 0; mi < 2; mi++) {
        uint32_t rowa = QS + (uint32_t)(wrow + mi*16 + (lane & 15)) * QROWB
                      + (uint32_t)((lane >> 4) << 4);
        #pragma unroll
        for (int k = 0; k < 4; k++) ldm_x4(qf[mi][k], rowa + k*32);
    }

    float oc[2][8][4];
    #pragma unroll
    for (int mi = 0; mi < 2; mi++)
        #pragma unroll
        for (int n = 0; n < 8; n++)
            #pragma unroll
            for (int q = 0; q < 4; q++) oc[mi][n][q] = 0.0f;
    ull lacc[2][2];
    lacc[0][0] = lacc[0][1] = lacc[1][0] = lacc[1][1] = pack2(0.0f, 0.0f);

    #pragma unroll 1
    for (int kt = 0; kt < NT; ++kt) {
        if (kt >= NT - 2) asm volatile("cp.async.wait_group 0;" ::: "memory");
        else              asm volatile("cp.async.wait_group 1;" ::: "memory");
        __syncthreads();   // single barrier per tile

        const uint32_t Kb = KV0 + (uint32_t)(kt % 3) * KVBUF;
        const uint32_t Vb = Kb + KTILE;

        float sc[2][8][4];
        #pragma unroll
        for (int mi = 0; mi < 2; mi++)
            #pragma unroll
            for (int n = 0; n < 8; n++)
                #pragma unroll
                for (int q = 0; q < 4; q++) sc[mi][n][q] = 0.0f;

        #pragma unroll
        for (int kk = 0; kk < 4; kk++) {
            uint32_t br[4][4];
            #pragma unroll
            for (int np = 0; np < 4; np++)
                ldm_x4(br[np], Kb + (uint32_t)(np*16 + ((lane >> 4) << 3) + (lane & 7)) * KROWB
                                 + (uint32_t)(kk*16 + (((lane >> 3) & 1) << 3)) * 2);
            #pragma unroll
            for (int mi = 0; mi < 2; mi++) {
                #pragma unroll
                for (int np = 0; np < 4; np++) {
                    mma_fp(sc[mi][np*2],   qf[mi][kk], &br[np][0]);
                    mma_fp(sc[mi][np*2+1], qf[mi][kk], &br[np][2]);
                }
            }
        }

        // prefetch into stage (kt+2)%3 = (kt-1)%3, consumed at kt-1; safe past the sync
        if (kt + 2 < NT) load_kv(kt + 2);

        // exp2 -> P (single fp16) -> PV (single term)
        #pragma unroll
        for (int kk = 0; kk < 4; kk++) {
            uint32_t aP[2][4];
            #pragma unroll
            for (int mi = 0; mi < 2; mi++) {
                #pragma unroll
                for (int half = 0; half < 2; half++) {
                    int n = 2*kk + half;
                    ull p01 = exp2pair(pack2(sc[mi][n][0], sc[mi][n][1]));
                    ull p23 = exp2pair(pack2(sc[mi][n][2], sc[mi][n][3]));
                    lacc[mi][0] = add2(lacc[mi][0], p01);
                    lacc[mi][1] = add2(lacc[mi][1], p23);
                    aP[mi][half*2]   = h2pack(unpack2(p01));
                    aP[mi][half*2+1] = h2pack(unpack2(p23));
                }
            }
            const uint32_t krow = (uint32_t)(kk*16 + ((lane >> 3) & 1) * 8 + (lane & 7));
            #pragma unroll
            for (int nb = 0; nb < 4; nb++) {
                uint32_t bv[4];
                ldm_x4_t(bv, Vb + krow * VROWB + (uint32_t)(nb*16 + ((lane >> 4) << 3)) * 2);
                #pragma unroll
                for (int mi = 0; mi < 2; mi++) {
                    mma_fp(oc[mi][nb*2],   aP[mi], &bv[0]);
                    mma_fp(oc[mi][nb*2+1], aP[mi], &bv[2]);
                }
            }
        }
    }

    // normalize + single-fp16 write to [B,N,H*D]
    #pragma unroll
    for (int mi = 0; mi < 2; mi++) {
        float2 L0 = unpack2(lacc[mi][0]);
        float l0 = L0.x + L0.y;
        l0 += __shfl_xor_sync(0xFFFFFFFFu, l0, 1);
        l0 += __shfl_xor_sync(0xFFFFFFFFu, l0, 2);
        float2 L1 = unpack2(lacc[mi][1]);
        float l1 = L1.x + L1.y;
        l1 += __shfl_xor_sync(0xFFFFFFFFu, l1, 1);
        l1 += __shfl_xor_sync(0xFFFFFFFFu, l1, 2);
        float inv0 = 1.0f / l0, inv1 = 1.0f / l1;
        int r0 = qt * 128 + wrow + mi*16 + (lane >> 2);
        #pragma unroll
        for (int ni = 0; ni < 8; ni++) {
            int d = ni*8 + (lane & 3)*2;
            size_t i0 = ((size_t)(b * SEQ + r0)) * CDIM + h * HD + d;
            size_t i1 = ((size_t)(b * SEQ + r0 + 8)) * CDIM + h * HD + d;
            store_h2(g_Oh, i0, oc[mi][ni][0]*inv0, oc[mi][ni][1]*inv0);
            store_h2(g_Oh, i1, oc[mi][ni][2]*inv1, oc[mi][ni][3]*inv1);
        }
    }
}

// ---------------- launch ----------------
extern "C" void kernel_launch(void* const* d_in, const int* in_sizes, int n_in,
                              void* d_out, int out_size)
{
    const float* x      = (const float*)d_in[0];
    const float* W_qkv  = (const float*)d_in[1];
    const float* b_qkv  = (const float*)d_in[2];
    const float* W_proj = (const float*)d_in[3];
    const float* b_proj = (const float*)d_in[4];
    float* out = (float*)d_out;

    cudaFuncSetAttribute(attn_mma, cudaFuncAttributeMaxDynamicSharedMemorySize, ATTN_SMEM);
    cudaFuncSetAttribute(gemm_fp16<0>, cudaFuncAttributeMaxDynamicSharedMemorySize, GEMM_SMEM);
    cudaFuncSetAttribute(gemm_fp16<1>, cudaFuncAttributeMaxDynamicSharedMemorySize, GEMM_SMEM);

    conv_x<<<(MROWS * KDIM / 4 + 255) / 256, 256>>>(x, MROWS * KDIM / 4);
    {
        dim3 bdim(32, 8);
        dim3 gq(NQKV / 32, KDIM / 32);
        conv_w<0><<<gq, bdim>>>(W_qkv, NQKV);
        dim3 gp(CDIM / 32, KDIM / 32);
        conv_w<1><<<gp, bdim>>>(W_proj, CDIM);
    }
    {
        dim3 g(NQKV / 128, MROWS / 128);
        gemm_fp16<0><<<g, 256, GEMM_SMEM>>>(b_qkv, nullptr);
    }
    {
        dim3 ga(SEQ / 128, BB * NH);
        attn_mma<<<ga, 128, ATTN_SMEM>>>();
    }
    {
        dim3 g(CDIM / 128, MROWS / 128);
        gemm_fp16<1><<<g, 256, GEMM_SMEM>>>(b_proj, out);
    }
}